// round 7
// baseline (speedup 1.0000x reference)
#include <cuda_runtime.h>

// Shapes (fixed by the problem)
#define BB  8
#define CC  512
#define LL  2048
#define CQ  64
#define SCALE 0.125f   // CQK^-0.5 = 64^-0.5

// ---------------------------------------------------------------------------
// Scratch (static __device__ arrays: no allocation anywhere, per harness rules)
// ---------------------------------------------------------------------------
__device__ float g_q[(size_t)BB * CQ * LL];          //  4 MB
__device__ float g_k[(size_t)BB * CQ * LL];          //  4 MB
__device__ float g_v[(size_t)BB * CC * LL];          // 33.5 MB
__device__ float g_attn[(size_t)BB * LL * LL];       // 134 MB
__device__ float g_av[(size_t)BB * CC * LL];         // 33.5 MB

// ---------------------------------------------------------------------------
// Kernel 1: fused QKV projection.
//   rows 0..63  -> q = Wq@x + bq      (row tile 0)
//   rows 0..63  -> k = Wk@x + bk      (row tile 1)
//   rows 0..511 -> v = Wv@x + bv      (row tiles 2..9)
// GEMM: Out[M=64 tile, N=64 tile] over K=512 in 32-chunks.
// smem layout [K][M] / [K][N] so the inner loop reads are conflict-free.
// ---------------------------------------------------------------------------
__global__ __launch_bounds__(256) void qkv_kernel(
    const float* __restrict__ x,
    const float* __restrict__ Wq, const float* __restrict__ bq,
    const float* __restrict__ Wk, const float* __restrict__ bk,
    const float* __restrict__ Wv, const float* __restrict__ bv)
{
    const int b  = blockIdx.z;
    const int rt = blockIdx.y;           // 0..9
    const int l0 = blockIdx.x * 64;

    const float* W;  const float* bias;  float* out;  int row0;
    if (rt == 0)      { W = Wq; bias = bq; out = g_q + (size_t)b * CQ * LL; row0 = 0; }
    else if (rt == 1) { W = Wk; bias = bk; out = g_k + (size_t)b * CQ * LL; row0 = 0; }
    else              { W = Wv; bias = bv; out = g_v + (size_t)b * CC * LL; row0 = (rt - 2) * 64; }

    __shared__ float As[32][65];   // [k][m]  (65: stride-65 writes hit distinct banks)
    __shared__ float Bs[32][64];   // [k][n]

    const int tid = threadIdx.x;
    const int tx = tid & 15, ty = tid >> 4;
    const float* xb = x + (size_t)b * CC * LL;

    float acc[4][4] = {};

    for (int k0 = 0; k0 < CC; k0 += 32) {
        #pragma unroll
        for (int i = 0; i < 8; ++i) {
            int idx = tid + i * 256;                 // 0..2047
            int m  = idx >> 5, cc = idx & 31;       // W tile: [64 rows][32 k]
            As[cc][m] = W[(size_t)(row0 + m) * CC + k0 + cc];
        }
        #pragma unroll
        for (int i = 0; i < 8; ++i) {
            int idx = tid + i * 256;
            int cc = idx >> 6, n = idx & 63;        // X tile: [32 k][64 l], l contiguous
            Bs[cc][n] = xb[(size_t)(k0 + cc) * LL + l0 + n];
        }
        __syncthreads();
        #pragma unroll
        for (int kk = 0; kk < 32; ++kk) {
            float a[4], bv_[4];
            #pragma unroll
            for (int i = 0; i < 4; ++i) a[i]  = As[kk][ty * 4 + i];
            #pragma unroll
            for (int j = 0; j < 4; ++j) bv_[j] = Bs[kk][tx * 4 + j];
            #pragma unroll
            for (int i = 0; i < 4; ++i)
                #pragma unroll
                for (int j = 0; j < 4; ++j)
                    acc[i][j] += a[i] * bv_[j];
        }
        __syncthreads();
    }

    #pragma unroll
    for (int i = 0; i < 4; ++i) {
        int m = ty * 4 + i;
        float bsv = bias[row0 + m];
        #pragma unroll
        for (int j = 0; j < 4; ++j)
            out[(size_t)(row0 + m) * LL + l0 + tx * 4 + j] = acc[i][j] + bsv;
    }
}

// ---------------------------------------------------------------------------
// Kernel 2: scores S[b,q,k] = scale * sum_c q[b,c,q] * k[b,c,k]
// K dim = 64 (fits entirely in smem). Operands are already K(c)-major in
// gmem with q/k contiguous, so loads land straight into [c][n] layout.
// ---------------------------------------------------------------------------
__global__ __launch_bounds__(256) void scores_kernel()
{
    const int b  = blockIdx.z;
    const int q0 = blockIdx.y * 64;
    const int k0 = blockIdx.x * 64;

    __shared__ float Qs[64][64];   // [c][q]
    __shared__ float Ks[64][64];   // [c][k]

    const int tid = threadIdx.x;
    const int tx = tid & 15, ty = tid >> 4;
    const float* qb = g_q + (size_t)b * CQ * LL;
    const float* kb = g_k + (size_t)b * CQ * LL;

    #pragma unroll
    for (int i = 0; i < 16; ++i) {
        int idx = tid + i * 256;                    // 0..4095
        int c = idx >> 6, n = idx & 63;
        Qs[c][n] = qb[(size_t)c * LL + q0 + n];
        Ks[c][n] = kb[(size_t)c * LL + k0 + n];
    }
    __syncthreads();

    float acc[4][4] = {};
    #pragma unroll
    for (int cc = 0; cc < 64; ++cc) {
        float a[4], bv_[4];
        #pragma unroll
        for (int i = 0; i < 4; ++i) a[i]  = Qs[cc][ty * 4 + i];
        #pragma unroll
        for (int j = 0; j < 4; ++j) bv_[j] = Ks[cc][tx * 4 + j];
        #pragma unroll
        for (int i = 0; i < 4; ++i)
            #pragma unroll
            for (int j = 0; j < 4; ++j)
                acc[i][j] += a[i] * bv_[j];
    }

    float* sb = g_attn + (size_t)b * LL * LL;
    #pragma unroll
    for (int i = 0; i < 4; ++i)
        #pragma unroll
        for (int j = 0; j < 4; ++j)
            sb[(size_t)(q0 + ty * 4 + i) * LL + k0 + tx * 4 + j] = acc[i][j] * SCALE;
}

// ---------------------------------------------------------------------------
// Kernel 3: row softmax over the last axis of g_attn (in place).
// One block per (b, q) row of 2048; 8 elements per thread in registers.
// ---------------------------------------------------------------------------
__global__ __launch_bounds__(256) void softmax_kernel()
{
    const int b = blockIdx.y;
    const int q = blockIdx.x;
    float* row = g_attn + ((size_t)b * LL + q) * LL;
    const int tid = threadIdx.x;

    float v[8];
    float m = -1e30f;
    #pragma unroll
    for (int i = 0; i < 8; ++i) { v[i] = row[tid + i * 256]; m = fmaxf(m, v[i]); }

    __shared__ float red[256];
    red[tid] = m; __syncthreads();
    #pragma unroll
    for (int s = 128; s > 0; s >>= 1) {
        if (tid < s) red[tid] = fmaxf(red[tid], red[tid + s]);
        __syncthreads();
    }
    m = red[0];
    __syncthreads();

    float sum = 0.f;
    #pragma unroll
    for (int i = 0; i < 8; ++i) { v[i] = expf(v[i] - m); sum += v[i]; }
    red[tid] = sum; __syncthreads();
    #pragma unroll
    for (int s = 128; s > 0; s >>= 1) {
        if (tid < s) red[tid] += red[tid + s];
        __syncthreads();
    }
    const float inv = 1.0f / red[0];
    #pragma unroll
    for (int i = 0; i < 8; ++i) row[tid + i * 256] = v[i] * inv;
}

// ---------------------------------------------------------------------------
// Kernel 4: PV: g_av[b,c,q] = sum_k v[b,c,k] * attn[b,q,k]
// Both operands k-contiguous -> transposed smem stores ([k][m], [k][n]).
// Dominant stage: 34 GFLOP over K=2048.
// ---------------------------------------------------------------------------
__global__ __launch_bounds__(256) void pv_kernel()
{
    const int b  = blockIdx.z;
    const int c0 = blockIdx.y * 64;
    const int q0 = blockIdx.x * 64;

    __shared__ float Vs[32][65];   // [k][c]
    __shared__ float Ps[32][65];   // [k][q]

    const int tid = threadIdx.x;
    const int tx = tid & 15, ty = tid >> 4;
    const float* vb = g_v    + (size_t)b * CC * LL;
    const float* ab = g_attn + (size_t)b * LL * LL;

    float acc[4][4] = {};

    for (int k0 = 0; k0 < LL; k0 += 32) {
        #pragma unroll
        for (int i = 0; i < 8; ++i) {
            int idx = tid + i * 256;
            int m = idx >> 5, kk = idx & 31;        // k contiguous in gmem -> coalesced
            Vs[kk][m] = vb[(size_t)(c0 + m) * LL + k0 + kk];
            Ps[kk][m] = ab[(size_t)(q0 + m) * LL + k0 + kk];
        }
        __syncthreads();
        #pragma unroll
        for (int kk = 0; kk < 32; ++kk) {
            float a[4], bv_[4];
            #pragma unroll
            for (int i = 0; i < 4; ++i) a[i]  = Vs[kk][ty * 4 + i];
            #pragma unroll
            for (int j = 0; j < 4; ++j) bv_[j] = Ps[kk][tx * 4 + j];
            #pragma unroll
            for (int i = 0; i < 4; ++i)
                #pragma unroll
                for (int j = 0; j < 4; ++j)
                    acc[i][j] += a[i] * bv_[j];
        }
        __syncthreads();
    }

    float* ob = g_av + (size_t)b * CC * LL;
    #pragma unroll
    for (int i = 0; i < 4; ++i)
        #pragma unroll
        for (int j = 0; j < 4; ++j)
            ob[(size_t)(c0 + ty * 4 + i) * LL + q0 + tx * 4 + j] = acc[i][j];
}

// ---------------------------------------------------------------------------
// Kernel 5: output projection + bias + residual:
//   out[b,o,l] = sum_c Wo[o,c]*g_av[b,c,l] + bo[o] + x[b,o,l]
// ---------------------------------------------------------------------------
__global__ __launch_bounds__(256) void outproj_kernel(
    const float* __restrict__ x,
    const float* __restrict__ Wo, const float* __restrict__ bo,
    float* __restrict__ out)
{
    const int b  = blockIdx.z;
    const int r0 = blockIdx.y * 64;   // output channel tile
    const int l0 = blockIdx.x * 64;

    __shared__ float As[32][65];   // [k][m]
    __shared__ float Bs[32][64];   // [k][n]

    const int tid = threadIdx.x;
    const int tx = tid & 15, ty = tid >> 4;
    const float* avb = g_av + (size_t)b * CC * LL;

    float acc[4][4] = {};

    for (int k0 = 0; k0 < CC; k0 += 32) {
        #pragma unroll
        for (int i = 0; i < 8; ++i) {
            int idx = tid + i * 256;
            int m = idx >> 5, cc = idx & 31;
            As[cc][m] = Wo[(size_t)(r0 + m) * CC + k0 + cc];
        }
        #pragma unroll
        for (int i = 0; i < 8; ++i) {
            int idx = tid + i * 256;
            int cc = idx >> 6, n = idx & 63;
            Bs[cc][n] = avb[(size_t)(k0 + cc) * LL + l0 + n];
        }
        __syncthreads();
        #pragma unroll
        for (int kk = 0; kk < 32; ++kk) {
            float a[4], bv_[4];
            #pragma unroll
            for (int i = 0; i < 4; ++i) a[i]  = As[kk][ty * 4 + i];
            #pragma unroll
            for (int j = 0; j < 4; ++j) bv_[j] = Bs[kk][tx * 4 + j];
            #pragma unroll
            for (int i = 0; i < 4; ++i)
                #pragma unroll
                for (int j = 0; j < 4; ++j)
                    acc[i][j] += a[i] * bv_[j];
        }
        __syncthreads();
    }

    #pragma unroll
    for (int i = 0; i < 4; ++i) {
        int m = r0 + ty * 4 + i;
        float bsv = bo[m];
        #pragma unroll
        for (int j = 0; j < 4; ++j) {
            size_t off = (size_t)b * CC * LL + (size_t)m * LL + l0 + tx * 4 + j;
            out[off] = acc[i][j] + bsv + x[off];
        }
    }
}

// ---------------------------------------------------------------------------
// Launch: 5 kernels on one stream (implicit ordering), graph-capturable.
// ---------------------------------------------------------------------------
extern "C" void kernel_launch(void* const* d_in, const int* in_sizes, int n_in,
                              void* d_out, int out_size)
{
    (void)in_sizes; (void)n_in; (void)out_size;
    const float* x  = (const float*)d_in[0];
    const float* Wq = (const float*)d_in[1];
    const float* bq = (const float*)d_in[2];
    const float* Wk = (const float*)d_in[3];
    const float* bk = (const float*)d_in[4];
    const float* Wv = (const float*)d_in[5];
    const float* bv = (const float*)d_in[6];
    const float* Wo = (const float*)d_in[7];
    const float* bo = (const float*)d_in[8];
    float* out = (float*)d_out;

    dim3 blk(256);
    qkv_kernel    <<<dim3(LL / 64, 10,       BB), blk>>>(x, Wq, bq, Wk, bk, Wv, bv);
    scores_kernel <<<dim3(LL / 64, LL / 64,  BB), blk>>>();
    softmax_kernel<<<dim3(LL,      BB          ), blk>>>();
    pv_kernel     <<<dim3(LL / 64, CC / 64,  BB), blk>>>();
    outproj_kernel<<<dim3(LL / 64, CC / 64,  BB), blk>>>(x, Wo, bo, out);
}

// round 8
// speedup vs baseline: 2.6210x; 2.6210x over previous
#include <cuda_runtime.h>

// Shapes (fixed by the problem)
#define BB  8
#define CC  512
#define LL  2048
#define CQ  64
#define SCALE 0.125f   // CQK^-0.5

// ---------------------------------------------------------------------------
// Scratch (static __device__ arrays — no allocation anywhere)
// q/k/v/attn/av hold tf32-rounded values (valid fp32 bit patterns) so consumer
// kernels can feed them to mma.sync without any cvt in the hot loop.
// ---------------------------------------------------------------------------
__device__ float g_q[(size_t)BB * CQ * LL];          //  4 MB
__device__ float g_k[(size_t)BB * CQ * LL];          //  4 MB
__device__ float g_v[(size_t)BB * CC * LL];          // 33.5 MB
__device__ float g_attn[(size_t)BB * LL * LL];       // 134 MB
__device__ float g_av[(size_t)BB * CC * LL];         // 33.5 MB

// ---------------------------------------------------------------------------
// tf32 helpers
// ---------------------------------------------------------------------------
__device__ __forceinline__ unsigned f2tf(float f) {
    unsigned u; asm("cvt.rna.tf32.f32 %0, %1;" : "=r"(u) : "f"(f)); return u;
}
__device__ __forceinline__ float tfbits(float f) { return __uint_as_float(f2tf(f)); }

// D += A(16x8, row) * B(8x8, col); fp32 accum.
__device__ __forceinline__ void mma_tf32(float* c, const unsigned* a, const unsigned* b) {
    asm volatile(
        "mma.sync.aligned.m16n8k8.row.col.f32.tf32.tf32.f32 "
        "{%0,%1,%2,%3}, {%4,%5,%6,%7}, {%8,%9}, {%0,%1,%2,%3};"
        : "+f"(c[0]), "+f"(c[1]), "+f"(c[2]), "+f"(c[3])
        : "r"(a[0]), "r"(a[1]), "r"(a[2]), "r"(a[3]), "r"(b[0]), "r"(b[1]));
}

// Fragment maps (lane = g*4+t, g=lane>>2, t=lane&3):
//   A: a0=A[g][t]  a1=A[g+8][t]  a2=A[g][t+4]  a3=A[g+8][t+4]
//   B: b0=B[t][g]  b1=B[t+4][g]          (B indexed [k][n])
//   C: c0=C[g][2t] c1=C[g][2t+1] c2=C[g+8][2t] c3=C[g+8][2t+1]

// ---------------------------------------------------------------------------
// Kernel 1: fused QKV projection (tensor core).
// Block tile M=64, N=128, Kstep=32. 8 warps as 2(M)x4(N) -> warp 32x32.
//   As[m][k] pad 36  (W, cvt at stage)   frag banks (4g+t): conflict-free
//   Bs[k][n] pad 136 (x, cvt at stage)   frag banks (8t+g): conflict-free
// ---------------------------------------------------------------------------
__global__ __launch_bounds__(256) void qkv_kernel(
    const float* __restrict__ x,
    const float* __restrict__ Wq, const float* __restrict__ bq,
    const float* __restrict__ Wk, const float* __restrict__ bk,
    const float* __restrict__ Wv, const float* __restrict__ bv)
{
    const int b  = blockIdx.z;
    const int rt = blockIdx.y;           // 0..9
    const int l0 = blockIdx.x * 128;

    const float* W;  const float* bias;  float* out;  int row0;
    if (rt == 0)      { W = Wq; bias = bq; out = g_q + (size_t)b * CQ * LL; row0 = 0; }
    else if (rt == 1) { W = Wk; bias = bk; out = g_k + (size_t)b * CQ * LL; row0 = 0; }
    else              { W = Wv; bias = bv; out = g_v + (size_t)b * CC * LL; row0 = (rt - 2) * 64; }

    __shared__ float As[64][36];
    __shared__ float Bs[32][136];

    const int tid = threadIdx.x, w = tid >> 5, lane = tid & 31;
    const int g = lane >> 2, t = lane & 3;
    const int wm = (w >> 2) * 32, wn = (w & 3) * 32;
    const float* xb = x + (size_t)b * CC * LL;

    float acc[2][4][4] = {};

    for (int k0 = 0; k0 < CC; k0 += 32) {
        #pragma unroll
        for (int i = 0; i < 8; ++i) {
            int idx = tid + i * 256, m = idx >> 5, k = idx & 31;
            As[m][k] = tfbits(W[(size_t)(row0 + m) * CC + k0 + k]);
        }
        #pragma unroll
        for (int i = 0; i < 16; ++i) {
            int idx = tid + i * 256, k = idx >> 7, n = idx & 127;
            Bs[k][n] = tfbits(xb[(size_t)(k0 + k) * LL + l0 + n]);
        }
        __syncthreads();
        #pragma unroll
        for (int ks = 0; ks < 4; ++ks) {
            const int kk = ks * 8;
            unsigned af[2][4], bf[4][2];
            #pragma unroll
            for (int mi = 0; mi < 2; ++mi) {
                int mb = wm + mi * 16;
                af[mi][0] = __float_as_uint(As[mb + g    ][kk + t    ]);
                af[mi][1] = __float_as_uint(As[mb + g + 8][kk + t    ]);
                af[mi][2] = __float_as_uint(As[mb + g    ][kk + t + 4]);
                af[mi][3] = __float_as_uint(As[mb + g + 8][kk + t + 4]);
            }
            #pragma unroll
            for (int ni = 0; ni < 4; ++ni) {
                int nb = wn + ni * 8;
                bf[ni][0] = __float_as_uint(Bs[kk + t    ][nb + g]);
                bf[ni][1] = __float_as_uint(Bs[kk + t + 4][nb + g]);
            }
            #pragma unroll
            for (int mi = 0; mi < 2; ++mi)
                #pragma unroll
                for (int ni = 0; ni < 4; ++ni)
                    mma_tf32(acc[mi][ni], af[mi], bf[ni]);
        }
        __syncthreads();
    }

    #pragma unroll
    for (int mi = 0; mi < 2; ++mi) {
        int r0r = row0 + wm + mi * 16 + g;
        int r1r = r0r + 8;
        float b0v = bias[r0r], b1v = bias[r1r];
        #pragma unroll
        for (int ni = 0; ni < 4; ++ni) {
            int col = l0 + wn + ni * 8 + 2 * t;
            float2 v0 = make_float2(tfbits(acc[mi][ni][0] + b0v), tfbits(acc[mi][ni][1] + b0v));
            float2 v1 = make_float2(tfbits(acc[mi][ni][2] + b1v), tfbits(acc[mi][ni][3] + b1v));
            *(float2*)&out[(size_t)r0r * LL + col] = v0;
            *(float2*)&out[(size_t)r1r * LL + col] = v1;
        }
    }
}

// ---------------------------------------------------------------------------
// Kernel 2: scores S[b,q,k] = scale * sum_c q[b,c,q] * k[b,c,k]  (tensor core)
// Block 128(q) x 128(k), Kstep=32 (CQ=64 -> 2 iters). Warps 2x4 -> warp 64x32.
// A is q^T: fragments read from Qs[c][q] (pad 136, banks 8t+g OK).
// B fragments read from Ks[c][k]       (pad 136, banks 8t+g OK).
// No staging cvt: g_q/g_k already tf32-rounded.
// ---------------------------------------------------------------------------
__global__ __launch_bounds__(256) void scores_kernel()
{
    const int b  = blockIdx.z;
    const int q0 = blockIdx.y * 128;
    const int k0 = blockIdx.x * 128;

    __shared__ float Qs[32][136];
    __shared__ float Ks[32][136];

    const int tid = threadIdx.x, w = tid >> 5, lane = tid & 31;
    const int g = lane >> 2, t = lane & 3;
    const int wm = (w >> 2) * 64, wn = (w & 3) * 32;
    const float* qb = g_q + (size_t)b * CQ * LL;
    const float* kb = g_k + (size_t)b * CQ * LL;

    float acc[4][4][4] = {};

    for (int c0 = 0; c0 < CQ; c0 += 32) {
        #pragma unroll
        for (int i = 0; i < 16; ++i) {
            int idx = tid + i * 256, c = idx >> 7, n = idx & 127;
            Qs[c][n] = qb[(size_t)(c0 + c) * LL + q0 + n];
            Ks[c][n] = kb[(size_t)(c0 + c) * LL + k0 + n];
        }
        __syncthreads();
        #pragma unroll
        for (int ks = 0; ks < 4; ++ks) {
            const int kk = ks * 8;
            unsigned af[4][4], bf[4][2];
            #pragma unroll
            for (int mi = 0; mi < 4; ++mi) {
                int mb = wm + mi * 16;
                af[mi][0] = __float_as_uint(Qs[kk + t    ][mb + g    ]);
                af[mi][1] = __float_as_uint(Qs[kk + t    ][mb + g + 8]);
                af[mi][2] = __float_as_uint(Qs[kk + t + 4][mb + g    ]);
                af[mi][3] = __float_as_uint(Qs[kk + t + 4][mb + g + 8]);
            }
            #pragma unroll
            for (int ni = 0; ni < 4; ++ni) {
                int nb = wn + ni * 8;
                bf[ni][0] = __float_as_uint(Ks[kk + t    ][nb + g]);
                bf[ni][1] = __float_as_uint(Ks[kk + t + 4][nb + g]);
            }
            #pragma unroll
            for (int mi = 0; mi < 4; ++mi)
                #pragma unroll
                for (int ni = 0; ni < 4; ++ni)
                    mma_tf32(acc[mi][ni], af[mi], bf[ni]);
        }
        __syncthreads();
    }

    float* sb = g_attn + (size_t)b * LL * LL;
    #pragma unroll
    for (int mi = 0; mi < 4; ++mi) {
        int r0r = q0 + wm + mi * 16 + g;
        int r1r = r0r + 8;
        #pragma unroll
        for (int ni = 0; ni < 4; ++ni) {
            int col = k0 + wn + ni * 8 + 2 * t;
            *(float2*)&sb[(size_t)r0r * LL + col] =
                make_float2(acc[mi][ni][0] * SCALE, acc[mi][ni][1] * SCALE);
            *(float2*)&sb[(size_t)r1r * LL + col] =
                make_float2(acc[mi][ni][2] * SCALE, acc[mi][ni][3] * SCALE);
        }
    }
}

// ---------------------------------------------------------------------------
// Kernel 3: row softmax, in place, float4 vectorized.
// Output tf32-rounded (consumed as mma operand by pv).
// ---------------------------------------------------------------------------
__global__ __launch_bounds__(256) void softmax_kernel()
{
    const int b = blockIdx.y, q = blockIdx.x;
    float4* row = reinterpret_cast<float4*>(g_attn + ((size_t)b * LL + q) * LL);
    const int tid = threadIdx.x;

    float4 u = row[tid], v = row[tid + 256];
    float m = fmaxf(fmaxf(fmaxf(u.x, u.y), fmaxf(u.z, u.w)),
                    fmaxf(fmaxf(v.x, v.y), fmaxf(v.z, v.w)));

    __shared__ float red[256];
    red[tid] = m; __syncthreads();
    #pragma unroll
    for (int s = 128; s > 0; s >>= 1) {
        if (tid < s) red[tid] = fmaxf(red[tid], red[tid + s]);
        __syncthreads();
    }
    m = red[0]; __syncthreads();

    u.x = __expf(u.x - m); u.y = __expf(u.y - m);
    u.z = __expf(u.z - m); u.w = __expf(u.w - m);
    v.x = __expf(v.x - m); v.y = __expf(v.y - m);
    v.z = __expf(v.z - m); v.w = __expf(v.w - m);
    float sum = (u.x + u.y + u.z + u.w) + (v.x + v.y + v.z + v.w);

    red[tid] = sum; __syncthreads();
    #pragma unroll
    for (int s = 128; s > 0; s >>= 1) {
        if (tid < s) red[tid] += red[tid + s];
        __syncthreads();
    }
    const float inv = 1.0f / red[0];

    u.x = tfbits(u.x * inv); u.y = tfbits(u.y * inv);
    u.z = tfbits(u.z * inv); u.w = tfbits(u.w * inv);
    v.x = tfbits(v.x * inv); v.y = tfbits(v.y * inv);
    v.z = tfbits(v.z * inv); v.w = tfbits(v.w * inv);
    row[tid] = u; row[tid + 256] = v;
}

// ---------------------------------------------------------------------------
// Kernel 4: PV: av[b,c,q] = sum_k v[b,c,k] * attn[b,q,k]   (tensor core)
// Block 128(c) x 128(q), Kstep=32, K total 2048. Warps 2x4 -> warp 64x32.
// NO TRANSPOSE: B(col-major k8xn8) element (k,n) = attn[q0+n][k] reads
// straight from row-major Ps[q][k] pad-36 (banks 4g+t, conflict-free).
// ---------------------------------------------------------------------------
__global__ __launch_bounds__(256) void pv_kernel()
{
    const int b  = blockIdx.z;
    const int c0 = blockIdx.y * 128;
    const int q0 = blockIdx.x * 128;

    __shared__ float As[128][36];   // v tile [c][k]
    __shared__ float Ps[128][36];   // attn tile [q][k]

    const int tid = threadIdx.x, w = tid >> 5, lane = tid & 31;
    const int g = lane >> 2, t = lane & 3;
    const int wm = (w >> 2) * 64, wn = (w & 3) * 32;
    const float* vb = g_v    + (size_t)b * CC * LL;
    const float* ab = g_attn + (size_t)b * LL * LL;

    float acc[4][4][4] = {};

    for (int k0 = 0; k0 < LL; k0 += 32) {
        #pragma unroll
        for (int i = 0; i < 16; ++i) {
            int idx = tid + i * 256, m = idx >> 5, k = idx & 31;
            As[m][k] = vb[(size_t)(c0 + m) * LL + k0 + k];
            Ps[m][k] = ab[(size_t)(q0 + m) * LL + k0 + k];
        }
        __syncthreads();
        #pragma unroll
        for (int ks = 0; ks < 4; ++ks) {
            const int kk = ks * 8;
            unsigned af[4][4], bf[4][2];
            #pragma unroll
            for (int mi = 0; mi < 4; ++mi) {
                int mb = wm + mi * 16;
                af[mi][0] = __float_as_uint(As[mb + g    ][kk + t    ]);
                af[mi][1] = __float_as_uint(As[mb + g + 8][kk + t    ]);
                af[mi][2] = __float_as_uint(As[mb + g    ][kk + t + 4]);
                af[mi][3] = __float_as_uint(As[mb + g + 8][kk + t + 4]);
            }
            #pragma unroll
            for (int ni = 0; ni < 4; ++ni) {
                int nb = wn + ni * 8;
                bf[ni][0] = __float_as_uint(Ps[nb + g][kk + t    ]);
                bf[ni][1] = __float_as_uint(Ps[nb + g][kk + t + 4]);
            }
            #pragma unroll
            for (int mi = 0; mi < 4; ++mi)
                #pragma unroll
                for (int ni = 0; ni < 4; ++ni)
                    mma_tf32(acc[mi][ni], af[mi], bf[ni]);
        }
        __syncthreads();
    }

    float* ob = g_av + (size_t)b * CC * LL;
    #pragma unroll
    for (int mi = 0; mi < 4; ++mi) {
        int r0r = c0 + wm + mi * 16 + g;
        int r1r = r0r + 8;
        #pragma unroll
        for (int ni = 0; ni < 4; ++ni) {
            int col = q0 + wn + ni * 8 + 2 * t;
            *(float2*)&ob[(size_t)r0r * LL + col] =
                make_float2(tfbits(acc[mi][ni][0]), tfbits(acc[mi][ni][1]));
            *(float2*)&ob[(size_t)r1r * LL + col] =
                make_float2(tfbits(acc[mi][ni][2]), tfbits(acc[mi][ni][3]));
        }
    }
}

// ---------------------------------------------------------------------------
// Kernel 5: output projection + bias + residual (tensor core, fp32 out).
// Block 128(o) x 128(l), Kstep=32 over C=512. Warps 2x4 -> warp 64x32.
// ---------------------------------------------------------------------------
__global__ __launch_bounds__(256) void outproj_kernel(
    const float* __restrict__ x,
    const float* __restrict__ Wo, const float* __restrict__ bo,
    float* __restrict__ out)
{
    const int b  = blockIdx.z;
    const int r0 = blockIdx.y * 128;
    const int l0 = blockIdx.x * 128;

    __shared__ float As[128][36];   // Wo tile [o][c] (cvt at stage)
    __shared__ float Bs[32][136];   // av tile [c][l] (already tf32)

    const int tid = threadIdx.x, w = tid >> 5, lane = tid & 31;
    const int g = lane >> 2, t = lane & 3;
    const int wm = (w >> 2) * 64, wn = (w & 3) * 32;
    const float* avb = g_av + (size_t)b * CC * LL;

    float acc[4][4][4] = {};

    for (int k0 = 0; k0 < CC; k0 += 32) {
        #pragma unroll
        for (int i = 0; i < 16; ++i) {
            int idx = tid + i * 256, m = idx >> 5, k = idx & 31;
            As[m][k] = tfbits(Wo[(size_t)(r0 + m) * CC + k0 + k]);
        }
        #pragma unroll
        for (int i = 0; i < 16; ++i) {
            int idx = tid + i * 256, k = idx >> 7, n = idx & 127;
            Bs[k][n] = avb[(size_t)(k0 + k) * LL + l0 + n];
        }
        __syncthreads();
        #pragma unroll
        for (int ks = 0; ks < 4; ++ks) {
            const int kk = ks * 8;
            unsigned af[4][4], bf[4][2];
            #pragma unroll
            for (int mi = 0; mi < 4; ++mi) {
                int mb = wm + mi * 16;
                af[mi][0] = __float_as_uint(As[mb + g    ][kk + t    ]);
                af[mi][1] = __float_as_uint(As[mb + g + 8][kk + t    ]);
                af[mi][2] = __float_as_uint(As[mb + g    ][kk + t + 4]);
                af[mi][3] = __float_as_uint(As[mb + g + 8][kk + t + 4]);
            }
            #pragma unroll
            for (int ni = 0; ni < 4; ++ni) {
                int nb = wn + ni * 8;
                bf[ni][0] = __float_as_uint(Bs[kk + t    ][nb + g]);
                bf[ni][1] = __float_as_uint(Bs[kk + t + 4][nb + g]);
            }
            #pragma unroll
            for (int mi = 0; mi < 4; ++mi)
                #pragma unroll
                for (int ni = 0; ni < 4; ++ni)
                    mma_tf32(acc[mi][ni], af[mi], bf[ni]);
        }
        __syncthreads();
    }

    #pragma unroll
    for (int mi = 0; mi < 4; ++mi) {
        int ch0 = r0 + wm + mi * 16 + g;
        int ch1 = ch0 + 8;
        float b0v = bo[ch0], b1v = bo[ch1];
        #pragma unroll
        for (int ni = 0; ni < 4; ++ni) {
            int col = l0 + wn + ni * 8 + 2 * t;
            size_t off0 = (size_t)b * CC * LL + (size_t)ch0 * LL + col;
            size_t off1 = (size_t)b * CC * LL + (size_t)ch1 * LL + col;
            float2 x0 = *(const float2*)&x[off0];
            float2 x1 = *(const float2*)&x[off1];
            *(float2*)&out[off0] = make_float2(acc[mi][ni][0] + b0v + x0.x,
                                               acc[mi][ni][1] + b0v + x0.y);
            *(float2*)&out[off1] = make_float2(acc[mi][ni][2] + b1v + x1.x,
                                               acc[mi][ni][3] + b1v + x1.y);
        }
    }
}

// ---------------------------------------------------------------------------
// Launch: 5 kernels on one stream, graph-capturable, no allocations.
// ---------------------------------------------------------------------------
extern "C" void kernel_launch(void* const* d_in, const int* in_sizes, int n_in,
                              void* d_out, int out_size)
{
    (void)in_sizes; (void)n_in; (void)out_size;
    const float* x  = (const float*)d_in[0];
    const float* Wq = (const float*)d_in[1];
    const float* bq = (const float*)d_in[2];
    const float* Wk = (const float*)d_in[3];
    const float* bk = (const float*)d_in[4];
    const float* Wv = (const float*)d_in[5];
    const float* bv = (const float*)d_in[6];
    const float* Wo = (const float*)d_in[7];
    const float* bo = (const float*)d_in[8];
    float* out = (float*)d_out;

    dim3 blk(256);
    qkv_kernel    <<<dim3(LL / 128, 10,        BB), blk>>>(x, Wq, bq, Wk, bk, Wv, bv);
    scores_kernel <<<dim3(LL / 128, LL / 128,  BB), blk>>>();
    softmax_kernel<<<dim3(LL,       BB           ), blk>>>();
    pv_kernel     <<<dim3(LL / 128, CC / 128,  BB), blk>>>();
    outproj_kernel<<<dim3(LL / 128, CC / 128,  BB), blk>>>(x, Wo, bo, out);
}

// round 9
// speedup vs baseline: 3.9793x; 1.5183x over previous
#include <cuda_runtime.h>

// Shapes (fixed by the problem)
#define BB  8
#define CC  512
#define LL  2048
#define CQ  64
#define SCALE 0.125f   // CQK^-0.5

// ---------------------------------------------------------------------------
// Scratch (static __device__ arrays — no allocation anywhere)
// q/k/v/attn(post-softmax)/av hold tf32-rounded values so consumer kernels
// feed mma.sync with zero cvt in the hot loop.
// ---------------------------------------------------------------------------
__device__ float g_q[(size_t)BB * CQ * LL];          //  4 MB
__device__ float g_k[(size_t)BB * CQ * LL];          //  4 MB
__device__ float g_v[(size_t)BB * CC * LL];          // 33.5 MB
__device__ float g_attn[(size_t)BB * LL * LL];       // 134 MB
__device__ float g_av[(size_t)BB * CC * LL];         // 33.5 MB

// ---------------------------------------------------------------------------
// Helpers
// ---------------------------------------------------------------------------
__device__ __forceinline__ unsigned f2tf(float f) {
    unsigned u; asm("cvt.rna.tf32.f32 %0, %1;" : "=r"(u) : "f"(f)); return u;
}
__device__ __forceinline__ float tfbits(float f) { return __uint_as_float(f2tf(f)); }

__device__ __forceinline__ void cp16(float* dst_smem, const float* src) {
    unsigned d = (unsigned)__cvta_generic_to_shared(dst_smem);
    asm volatile("cp.async.cg.shared.global [%0], [%1], 16;" :: "r"(d), "l"(src));
}
#define CP_COMMIT() asm volatile("cp.async.commit_group;")
#define CP_WAIT(N)  asm volatile("cp.async.wait_group " #N ";")

// D += A(16x8 row) * B(8x8 col), fp32 accum.
__device__ __forceinline__ void mma_tf32(float* c, const unsigned* a, const unsigned* b) {
    asm volatile(
        "mma.sync.aligned.m16n8k8.row.col.f32.tf32.tf32.f32 "
        "{%0,%1,%2,%3}, {%4,%5,%6,%7}, {%8,%9}, {%0,%1,%2,%3};"
        : "+f"(c[0]), "+f"(c[1]), "+f"(c[2]), "+f"(c[3])
        : "r"(a[0]), "r"(a[1]), "r"(a[2]), "r"(a[3]), "r"(b[0]), "r"(b[1]));
}
// Fragment maps (lane = 4g+t): A: a0=A[g][t] a1=A[g+8][t] a2=A[g][t+4] a3=A[g+8][t+4]
//                              B: b0=B[t][g] b1=B[t+4][g]   (B indexed [k][n])
//                              C: c0=C[g][2t] c1=C[g][2t+1] c2=C[g+8][2t] c3=C[g+8][2t+1]

// ---------------------------------------------------------------------------
// Kernel 1: fused QKV projection. Block M=64 x N=128, Kstep=32, double-buffered
// cp.async. Warps 2(M)x4(N) -> 32x32 each. W & x raw fp32 -> cvt at frag load.
//   As[64][36] (W)   frag banks 4g+t   |   Bs[32][136] (x)  frag banks 8t+g
// ---------------------------------------------------------------------------
#define QKV_SMEM_FLOATS (2*64*36 + 2*32*136)
__global__ __launch_bounds__(256) void qkv_kernel(
    const float* __restrict__ x,
    const float* __restrict__ Wq, const float* __restrict__ bq,
    const float* __restrict__ Wk, const float* __restrict__ bk,
    const float* __restrict__ Wv, const float* __restrict__ bv)
{
    extern __shared__ float sm[];
    float* As = sm;                 // [2][64][36]
    float* Bs = sm + 2 * 64 * 36;   // [2][32][136]

    const int b  = blockIdx.z;
    const int rt = blockIdx.y;           // 0..9
    const int l0 = blockIdx.x * 128;

    const float* W;  const float* bias;  float* out;  int row0;
    if (rt == 0)      { W = Wq; bias = bq; out = g_q + (size_t)b * CQ * LL; row0 = 0; }
    else if (rt == 1) { W = Wk; bias = bk; out = g_k + (size_t)b * CQ * LL; row0 = 0; }
    else              { W = Wv; bias = bv; out = g_v + (size_t)b * CC * LL; row0 = (rt - 2) * 64; }

    const int tid = threadIdx.x, w = tid >> 5, lane = tid & 31;
    const int g = lane >> 2, t = lane & 3;
    const int wm = (w >> 2) * 32, wn = (w & 3) * 32;
    const float* xb = x + (size_t)b * CC * LL;

    float acc[2][4][4] = {};

    auto stage = [&](int buf, int k0) {
        float* Ab = As + buf * 64 * 36;
        float* Bb = Bs + buf * 32 * 136;
        #pragma unroll
        for (int i = 0; i < 2; ++i) {                     // 64x32 W tile
            int idx = tid + i * 256, m = idx >> 3, k4 = (idx & 7) * 4;
            cp16(Ab + m * 36 + k4, W + (size_t)(row0 + m) * CC + k0 + k4);
        }
        #pragma unroll
        for (int i = 0; i < 4; ++i) {                     // 32x128 x tile
            int idx = tid + i * 256, k = idx >> 5, n4 = (idx & 31) * 4;
            cp16(Bb + k * 136 + n4, xb + (size_t)(k0 + k) * LL + l0 + n4);
        }
        CP_COMMIT();
    };

    stage(0, 0);
    for (int it = 0; it < CC / 32; ++it) {
        CP_WAIT(0); __syncthreads();
        if (it + 1 < CC / 32) stage((it + 1) & 1, (it + 1) * 32);
        const float* Ab = As + (it & 1) * 64 * 36;
        const float* Bb = Bs + (it & 1) * 32 * 136;
        #pragma unroll
        for (int ks = 0; ks < 4; ++ks) {
            const int kk = ks * 8;
            unsigned af[2][4], bf[4][2];
            #pragma unroll
            for (int mi = 0; mi < 2; ++mi) {
                int mb = wm + mi * 16;
                af[mi][0] = f2tf(Ab[(mb + g    ) * 36 + kk + t    ]);
                af[mi][1] = f2tf(Ab[(mb + g + 8) * 36 + kk + t    ]);
                af[mi][2] = f2tf(Ab[(mb + g    ) * 36 + kk + t + 4]);
                af[mi][3] = f2tf(Ab[(mb + g + 8) * 36 + kk + t + 4]);
            }
            #pragma unroll
            for (int ni = 0; ni < 4; ++ni) {
                int nb = wn + ni * 8;
                bf[ni][0] = f2tf(Bb[(kk + t    ) * 136 + nb + g]);
                bf[ni][1] = f2tf(Bb[(kk + t + 4) * 136 + nb + g]);
            }
            #pragma unroll
            for (int mi = 0; mi < 2; ++mi)
                #pragma unroll
                for (int ni = 0; ni < 4; ++ni)
                    mma_tf32(acc[mi][ni], af[mi], bf[ni]);
        }
    }

    #pragma unroll
    for (int mi = 0; mi < 2; ++mi) {
        int r0r = row0 + wm + mi * 16 + g;
        int r1r = r0r + 8;
        float b0v = bias[r0r], b1v = bias[r1r];
        #pragma unroll
        for (int ni = 0; ni < 4; ++ni) {
            int col = l0 + wn + ni * 8 + 2 * t;
            *(float2*)&out[(size_t)r0r * LL + col] =
                make_float2(tfbits(acc[mi][ni][0] + b0v), tfbits(acc[mi][ni][1] + b0v));
            *(float2*)&out[(size_t)r1r * LL + col] =
                make_float2(tfbits(acc[mi][ni][2] + b1v), tfbits(acc[mi][ni][3] + b1v));
        }
    }
}

// ---------------------------------------------------------------------------
// Kernel 2: scores S = scale*(q^T k). Block 128q x 128k. Full CQ=64 staged as
// two cp.async groups; compute first half while second is in flight.
// Qs/Ks [64][136]; both operands already tf32 (no cvt).
// ---------------------------------------------------------------------------
#define SC_SMEM_FLOATS (2*64*136)
__global__ __launch_bounds__(256) void scores_kernel()
{
    extern __shared__ float sm[];
    float* Qs = sm;              // [64][136]
    float* Ks = sm + 64 * 136;

    const int b  = blockIdx.z;
    const int q0 = blockIdx.y * 128;
    const int k0 = blockIdx.x * 128;

    const int tid = threadIdx.x, w = tid >> 5, lane = tid & 31;
    const int g = lane >> 2, t = lane & 3;
    const int wm = (w >> 2) * 64, wn = (w & 3) * 32;
    const float* qb = g_q + (size_t)b * CQ * LL;
    const float* kb = g_k + (size_t)b * CQ * LL;

    // stage c-half h (32 rows) as one commit group
    auto stage = [&](int h) {
        int cbase = h * 32;
        #pragma unroll
        for (int i = 0; i < 4; ++i) {
            int idx = tid + i * 256, c = cbase + (idx >> 5), n4 = (idx & 31) * 4;
            cp16(Qs + c * 136 + n4, qb + (size_t)c * LL + q0 + n4);
            cp16(Ks + c * 136 + n4, kb + (size_t)c * LL + k0 + n4);
        }
        CP_COMMIT();
    };
    stage(0);
    stage(1);

    float acc[4][4][4] = {};

    #pragma unroll
    for (int h = 0; h < 2; ++h) {
        if (h == 0) { CP_WAIT(1); } else { CP_WAIT(0); }
        __syncthreads();
        #pragma unroll
        for (int ks = 0; ks < 4; ++ks) {
            const int kk = h * 32 + ks * 8;
            unsigned af[4][4], bf[4][2];
            #pragma unroll
            for (int mi = 0; mi < 4; ++mi) {
                int mb = wm + mi * 16;
                af[mi][0] = __float_as_uint(Qs[(kk + t    ) * 136 + mb + g    ]);
                af[mi][1] = __float_as_uint(Qs[(kk + t    ) * 136 + mb + g + 8]);
                af[mi][2] = __float_as_uint(Qs[(kk + t + 4) * 136 + mb + g    ]);
                af[mi][3] = __float_as_uint(Qs[(kk + t + 4) * 136 + mb + g + 8]);
            }
            #pragma unroll
            for (int ni = 0; ni < 4; ++ni) {
                int nb = wn + ni * 8;
                bf[ni][0] = __float_as_uint(Ks[(kk + t    ) * 136 + nb + g]);
                bf[ni][1] = __float_as_uint(Ks[(kk + t + 4) * 136 + nb + g]);
            }
            #pragma unroll
            for (int mi = 0; mi < 4; ++mi)
                #pragma unroll
                for (int ni = 0; ni < 4; ++ni)
                    mma_tf32(acc[mi][ni], af[mi], bf[ni]);
        }
    }

    float* sb = g_attn + (size_t)b * LL * LL;
    #pragma unroll
    for (int mi = 0; mi < 4; ++mi) {
        int r0r = q0 + wm + mi * 16 + g;
        int r1r = r0r + 8;
        #pragma unroll
        for (int ni = 0; ni < 4; ++ni) {
            int col = k0 + wn + ni * 8 + 2 * t;
            *(float2*)&sb[(size_t)r0r * LL + col] =
                make_float2(acc[mi][ni][0] * SCALE, acc[mi][ni][1] * SCALE);
            *(float2*)&sb[(size_t)r1r * LL + col] =
                make_float2(acc[mi][ni][2] * SCALE, acc[mi][ni][3] * SCALE);
        }
    }
}

// ---------------------------------------------------------------------------
// Kernel 3: row softmax, in place, float4 vectorized; output tf32-rounded.
// ---------------------------------------------------------------------------
__global__ __launch_bounds__(256) void softmax_kernel()
{
    const int b = blockIdx.y, q = blockIdx.x;
    float4* row = reinterpret_cast<float4*>(g_attn + ((size_t)b * LL + q) * LL);
    const int tid = threadIdx.x;

    float4 u = row[tid], v = row[tid + 256];
    float m = fmaxf(fmaxf(fmaxf(u.x, u.y), fmaxf(u.z, u.w)),
                    fmaxf(fmaxf(v.x, v.y), fmaxf(v.z, v.w)));

    __shared__ float red[256];
    red[tid] = m; __syncthreads();
    #pragma unroll
    for (int s = 128; s > 0; s >>= 1) {
        if (tid < s) red[tid] = fmaxf(red[tid], red[tid + s]);
        __syncthreads();
    }
    m = red[0]; __syncthreads();

    u.x = __expf(u.x - m); u.y = __expf(u.y - m);
    u.z = __expf(u.z - m); u.w = __expf(u.w - m);
    v.x = __expf(v.x - m); v.y = __expf(v.y - m);
    v.z = __expf(v.z - m); v.w = __expf(v.w - m);
    float sum = (u.x + u.y + u.z + u.w) + (v.x + v.y + v.z + v.w);

    red[tid] = sum; __syncthreads();
    #pragma unroll
    for (int s = 128; s > 0; s >>= 1) {
        if (tid < s) red[tid] += red[tid + s];
        __syncthreads();
    }
    const float inv = 1.0f / red[0];

    u.x = tfbits(u.x * inv); u.y = tfbits(u.y * inv);
    u.z = tfbits(u.z * inv); u.w = tfbits(u.w * inv);
    v.x = tfbits(v.x * inv); v.y = tfbits(v.y * inv);
    v.z = tfbits(v.z * inv); v.w = tfbits(v.w * inv);
    row[tid] = u; row[tid + 256] = v;
}

// ---------------------------------------------------------------------------
// Kernel 4: PV: av[b,c,q] = sum_k v[b,c,k]*attn[b,q,k]. Block 128c x 128q,
// Kstep=32 over K=2048, double-buffered cp.async. No transpose anywhere:
//   As[128][36] = v[c][k]    frag banks 4g+t
//   Ps[128][36] = attn[q][k] B-frag b0 = Ps[nb+g][kk+t], banks 4g+t
// Both operands already tf32 -> zero cvt in hot loop.
// ---------------------------------------------------------------------------
#define PV_SMEM_FLOATS (4*128*36)
__global__ __launch_bounds__(256) void pv_kernel()
{
    extern __shared__ float sm[];
    float* As = sm;                  // [2][128][36]
    float* Ps = sm + 2 * 128 * 36;   // [2][128][36]

    const int b  = blockIdx.z;
    const int c0 = blockIdx.y * 128;
    const int q0 = blockIdx.x * 128;

    const int tid = threadIdx.x, w = tid >> 5, lane = tid & 31;
    const int g = lane >> 2, t = lane & 3;
    const int wm = (w >> 2) * 64, wn = (w & 3) * 32;
    const float* vb = g_v    + (size_t)b * CC * LL;
    const float* ab = g_attn + (size_t)b * LL * LL;

    float acc[4][4][4] = {};

    auto stage = [&](int buf, int k0) {
        float* Ab = As + buf * 128 * 36;
        float* Pb = Ps + buf * 128 * 36;
        #pragma unroll
        for (int i = 0; i < 4; ++i) {
            int idx = tid + i * 256, m = idx >> 3, k4 = (idx & 7) * 4;
            cp16(Ab + m * 36 + k4, vb + (size_t)(c0 + m) * LL + k0 + k4);
            cp16(Pb + m * 36 + k4, ab + (size_t)(q0 + m) * LL + k0 + k4);
        }
        CP_COMMIT();
    };

    stage(0, 0);
    for (int it = 0; it < LL / 32; ++it) {
        CP_WAIT(0); __syncthreads();
        if (it + 1 < LL / 32) stage((it + 1) & 1, (it + 1) * 32);
        const float* Ab = As + (it & 1) * 128 * 36;
        const float* Pb = Ps + (it & 1) * 128 * 36;
        #pragma unroll
        for (int ks = 0; ks < 4; ++ks) {
            const int kk = ks * 8;
            unsigned af[4][4], bf[4][2];
            #pragma unroll
            for (int mi = 0; mi < 4; ++mi) {
                int mb = wm + mi * 16;
                af[mi][0] = __float_as_uint(Ab[(mb + g    ) * 36 + kk + t    ]);
                af[mi][1] = __float_as_uint(Ab[(mb + g + 8) * 36 + kk + t    ]);
                af[mi][2] = __float_as_uint(Ab[(mb + g    ) * 36 + kk + t + 4]);
                af[mi][3] = __float_as_uint(Ab[(mb + g + 8) * 36 + kk + t + 4]);
            }
            #pragma unroll
            for (int ni = 0; ni < 4; ++ni) {
                int nb = wn + ni * 8;
                bf[ni][0] = __float_as_uint(Pb[(nb + g) * 36 + kk + t    ]);
                bf[ni][1] = __float_as_uint(Pb[(nb + g) * 36 + kk + t + 4]);
            }
            #pragma unroll
            for (int mi = 0; mi < 4; ++mi)
                #pragma unroll
                for (int ni = 0; ni < 4; ++ni)
                    mma_tf32(acc[mi][ni], af[mi], bf[ni]);
        }
    }

    float* ob = g_av + (size_t)b * CC * LL;
    #pragma unroll
    for (int mi = 0; mi < 4; ++mi) {
        int r0r = c0 + wm + mi * 16 + g;
        int r1r = r0r + 8;
        #pragma unroll
        for (int ni = 0; ni < 4; ++ni) {
            int col = q0 + wn + ni * 8 + 2 * t;
            *(float2*)&ob[(size_t)r0r * LL + col] =
                make_float2(tfbits(acc[mi][ni][0]), tfbits(acc[mi][ni][1]));
            *(float2*)&ob[(size_t)r1r * LL + col] =
                make_float2(tfbits(acc[mi][ni][2]), tfbits(acc[mi][ni][3]));
        }
    }
}

// ---------------------------------------------------------------------------
// Kernel 5: O projection + bias + residual. Block 128o x 128l, Kstep=32,
// double-buffered cp.async. Wo raw fp32 (cvt at frag), av already tf32.
// ---------------------------------------------------------------------------
#define OP_SMEM_FLOATS (2*128*36 + 2*32*136)
__global__ __launch_bounds__(256) void outproj_kernel(
    const float* __restrict__ x,
    const float* __restrict__ Wo, const float* __restrict__ bo,
    float* __restrict__ out)
{
    extern __shared__ float sm[];
    float* As = sm;                  // [2][128][36]  Wo tile
    float* Bs = sm + 2 * 128 * 36;   // [2][32][136]  av tile

    const int b  = blockIdx.z;
    const int r0 = blockIdx.y * 128;
    const int l0 = blockIdx.x * 128;

    const int tid = threadIdx.x, w = tid >> 5, lane = tid & 31;
    const int g = lane >> 2, t = lane & 3;
    const int wm = (w >> 2) * 64, wn = (w & 3) * 32;
    const float* avb = g_av + (size_t)b * CC * LL;

    float acc[4][4][4] = {};

    auto stage = [&](int buf, int k0) {
        float* Ab = As + buf * 128 * 36;
        float* Bb = Bs + buf * 32 * 136;
        #pragma unroll
        for (int i = 0; i < 4; ++i) {
            int idx = tid + i * 256, m = idx >> 3, k4 = (idx & 7) * 4;
            cp16(Ab + m * 36 + k4, Wo + (size_t)(r0 + m) * CC + k0 + k4);
        }
        #pragma unroll
        for (int i = 0; i < 4; ++i) {
            int idx = tid + i * 256, k = idx >> 5, n4 = (idx & 31) * 4;
            cp16(Bb + k * 136 + n4, avb + (size_t)(k0 + k) * LL + l0 + n4);
        }
        CP_COMMIT();
    };

    stage(0, 0);
    for (int it = 0; it < CC / 32; ++it) {
        CP_WAIT(0); __syncthreads();
        if (it + 1 < CC / 32) stage((it + 1) & 1, (it + 1) * 32);
        const float* Ab = As + (it & 1) * 128 * 36;
        const float* Bb = Bs + (it & 1) * 32 * 136;
        #pragma unroll
        for (int ks = 0; ks < 4; ++ks) {
            const int kk = ks * 8;
            unsigned af[4][4], bf[4][2];
            #pragma unroll
            for (int mi = 0; mi < 4; ++mi) {
                int mb = wm + mi * 16;
                af[mi][0] = f2tf(Ab[(mb + g    ) * 36 + kk + t    ]);
                af[mi][1] = f2tf(Ab[(mb + g + 8) * 36 + kk + t    ]);
                af[mi][2] = f2tf(Ab[(mb + g    ) * 36 + kk + t + 4]);
                af[mi][3] = f2tf(Ab[(mb + g + 8) * 36 + kk + t + 4]);
            }
            #pragma unroll
            for (int ni = 0; ni < 4; ++ni) {
                int nb = wn + ni * 8;
                bf[ni][0] = __float_as_uint(Bb[(kk + t    ) * 136 + nb + g]);
                bf[ni][1] = __float_as_uint(Bb[(kk + t + 4) * 136 + nb + g]);
            }
            #pragma unroll
            for (int mi = 0; mi < 4; ++mi)
                #pragma unroll
                for (int ni = 0; ni < 4; ++ni)
                    mma_tf32(acc[mi][ni], af[mi], bf[ni]);
        }
    }

    #pragma unroll
    for (int mi = 0; mi < 4; ++mi) {
        int ch0 = r0 + wm + mi * 16 + g;
        int ch1 = ch0 + 8;
        float b0v = bo[ch0], b1v = bo[ch1];
        #pragma unroll
        for (int ni = 0; ni < 4; ++ni) {
            int col = l0 + wn + ni * 8 + 2 * t;
            size_t off0 = (size_t)b * CC * LL + (size_t)ch0 * LL + col;
            size_t off1 = (size_t)b * CC * LL + (size_t)ch1 * LL + col;
            float2 x0 = *(const float2*)&x[off0];
            float2 x1 = *(const float2*)&x[off1];
            *(float2*)&out[off0] = make_float2(acc[mi][ni][0] + b0v + x0.x,
                                               acc[mi][ni][1] + b0v + x0.y);
            *(float2*)&out[off1] = make_float2(acc[mi][ni][2] + b1v + x1.x,
                                               acc[mi][ni][3] + b1v + x1.y);
        }
    }
}

// ---------------------------------------------------------------------------
// Launch: 5 kernels on one stream, graph-capturable, no allocations.
// Dynamic smem (>48KB) via cudaFuncSetAttribute (host-side, capture-safe,
// idempotent — no static guards needed).
// ---------------------------------------------------------------------------
extern "C" void kernel_launch(void* const* d_in, const int* in_sizes, int n_in,
                              void* d_out, int out_size)
{
    (void)in_sizes; (void)n_in; (void)out_size;
    const float* x  = (const float*)d_in[0];
    const float* Wq = (const float*)d_in[1];
    const float* bq = (const float*)d_in[2];
    const float* Wk = (const float*)d_in[3];
    const float* bk = (const float*)d_in[4];
    const float* Wv = (const float*)d_in[5];
    const float* bv = (const float*)d_in[6];
    const float* Wo = (const float*)d_in[7];
    const float* bo = (const float*)d_in[8];
    float* out = (float*)d_out;

    const int qkv_sm = QKV_SMEM_FLOATS * 4;   // 53248 B
    const int sc_sm  = SC_SMEM_FLOATS  * 4;   // 69632 B
    const int pv_sm  = PV_SMEM_FLOATS  * 4;   // 73728 B
    const int op_sm  = OP_SMEM_FLOATS  * 4;   // 71680 B

    cudaFuncSetAttribute(qkv_kernel,     cudaFuncAttributeMaxDynamicSharedMemorySize, qkv_sm);
    cudaFuncSetAttribute(scores_kernel,  cudaFuncAttributeMaxDynamicSharedMemorySize, sc_sm);
    cudaFuncSetAttribute(pv_kernel,      cudaFuncAttributeMaxDynamicSharedMemorySize, pv_sm);
    cudaFuncSetAttribute(outproj_kernel, cudaFuncAttributeMaxDynamicSharedMemorySize, op_sm);

    dim3 blk(256);
    qkv_kernel    <<<dim3(LL / 128, 10,        BB), blk, qkv_sm>>>(x, Wq, bq, Wk, bk, Wv, bv);
    scores_kernel <<<dim3(LL / 128, LL / 128,  BB), blk, sc_sm>>>();
    softmax_kernel<<<dim3(LL,       BB           ), blk>>>();
    pv_kernel     <<<dim3(LL / 128, CC / 128,  BB), blk, pv_sm>>>();
    outproj_kernel<<<dim3(LL / 128, CC / 128,  BB), blk, op_sm>>>(x, Wo, bo, out);
}

// round 10
// speedup vs baseline: 4.2330x; 1.0637x over previous
#include <cuda_runtime.h>

// Shapes (fixed by the problem)
#define BB  8
#define CC  512
#define LL  2048
#define CQ  64
#define SCALE 0.125f   // CQK^-0.5

// ---------------------------------------------------------------------------
// Scratch (static __device__ arrays — no allocation anywhere)
// ---------------------------------------------------------------------------
__device__ float g_q[(size_t)BB * CQ * LL];          //  4 MB
__device__ float g_k[(size_t)BB * CQ * LL];          //  4 MB
__device__ float g_v[(size_t)BB * CC * LL];          // 33.5 MB
__device__ float g_attn[(size_t)BB * LL * LL];       // 134 MB
__device__ float g_av[(size_t)BB * CC * LL];         // 33.5 MB

// ---------------------------------------------------------------------------
// Helpers
// ---------------------------------------------------------------------------
__device__ __forceinline__ void cp16(float* dst_smem, const float* src) {
    unsigned d = (unsigned)__cvta_generic_to_shared(dst_smem);
    asm volatile("cp.async.cg.shared.global [%0], [%1], 16;" :: "r"(d), "l"(src));
}
#define CP_COMMIT() asm volatile("cp.async.commit_group;")
#define CP_WAIT(N)  asm volatile("cp.async.wait_group " #N ";")

// ldmatrix: an 8x8 .b16 matrix (8 rows x 16B) == an 8x4 tf32 tile; output map
// lane l -> (row l>>2, 32-bit col l&3) == tf32 mma A/B fragment element map.
__device__ __forceinline__ void ldsm_x4(unsigned* r, unsigned saddr) {
    asm volatile("ldmatrix.sync.aligned.m8n8.x4.shared.b16 {%0,%1,%2,%3}, [%4];"
        : "=r"(r[0]), "=r"(r[1]), "=r"(r[2]), "=r"(r[3]) : "r"(saddr));
}
__device__ __forceinline__ void ldsm_x2(unsigned* r, unsigned saddr) {
    asm volatile("ldmatrix.sync.aligned.m8n8.x2.shared.b16 {%0,%1}, [%2];"
        : "=r"(r[0]), "=r"(r[1]) : "r"(saddr));
}

// D += A(16x8 row) * B(8x8 col), fp32 accum. HW ignores low 13 operand bits.
__device__ __forceinline__ void mma_tf32(float* c, const unsigned* a, const unsigned* b) {
    asm volatile(
        "mma.sync.aligned.m16n8k8.row.col.f32.tf32.tf32.f32 "
        "{%0,%1,%2,%3}, {%4,%5,%6,%7}, {%8,%9}, {%0,%1,%2,%3};"
        : "+f"(c[0]), "+f"(c[1]), "+f"(c[2]), "+f"(c[3])
        : "r"(a[0]), "r"(a[1]), "r"(a[2]), "r"(a[3]), "r"(b[0]), "r"(b[1]));
}
// Fragment maps (lane = 4g+t): A: a0=A[g][t] a1=A[g+8][t] a2=A[g][t+4] a3=A[g+8][t+4]
//                              B: b0=B[t][g] b1=B[t+4][g]   (B indexed [k][n])
//                              C: c0=C[g][2t] c1=C[g][2t+1] c2=C[g+8][2t] c3=C[g+8][2t+1]
// ldmatrix lane->address (x4): mat = l>>3; rows l&7; mats {0,1}=cols k..k+3 rows {+0,+8},
// mats {2,3}=cols k+4..k+7 rows {+0,+8}  -> r0..r3 == a0..a3 exactly.

// ---------------------------------------------------------------------------
// Kernel 1: fused QKV projection. Block M=64 x N=128, Kstep=32, 3-stage
// cp.async pipeline. Warps 2(M)x4(N). A-frags via LDSM; B scalar LDS.
//   As[64][36] (W)  |  Bs[32][136] (x)
// ---------------------------------------------------------------------------
#define QKV_STAGES 3
#define QKV_AF (64*36)
#define QKV_BF (32*136)
#define QKV_SMEM_FLOATS (QKV_STAGES*(QKV_AF+QKV_BF))
__global__ __launch_bounds__(256) void qkv_kernel(
    const float* __restrict__ x,
    const float* __restrict__ Wq, const float* __restrict__ bq,
    const float* __restrict__ Wk, const float* __restrict__ bk,
    const float* __restrict__ Wv, const float* __restrict__ bv)
{
    extern __shared__ float sm[];
    float* As = sm;                        // [3][64][36]
    float* Bs = sm + QKV_STAGES * QKV_AF;  // [3][32][136]

    const int b  = blockIdx.z;
    const int rt = blockIdx.y;           // 0..9
    const int l0 = blockIdx.x * 128;

    const float* W;  const float* bias;  float* out;  int row0;
    if (rt == 0)      { W = Wq; bias = bq; out = g_q + (size_t)b * CQ * LL; row0 = 0; }
    else if (rt == 1) { W = Wk; bias = bk; out = g_k + (size_t)b * CQ * LL; row0 = 0; }
    else              { W = Wv; bias = bv; out = g_v + (size_t)b * CC * LL; row0 = (rt - 2) * 64; }

    const int tid = threadIdx.x, w = tid >> 5, lane = tid & 31;
    const int g = lane >> 2, t = lane & 3;
    const int wm = (w >> 2) * 32, wn = (w & 3) * 32;
    const float* xb = x + (size_t)b * CC * LL;

    // ldmatrix per-lane offsets (A)
    const int arow = ((lane >> 3) & 1) * 8 + (lane & 7);
    const int acol = (lane >> 4) * 4;
    const unsigned smA = (unsigned)__cvta_generic_to_shared(As);

    float acc[2][4][4] = {};

    auto stage = [&](int buf, int k0) {
        float* Ab = As + buf * QKV_AF;
        float* Bb = Bs + buf * QKV_BF;
        #pragma unroll
        for (int i = 0; i < 2; ++i) {                     // 64x32 W tile
            int idx = tid + i * 256, m = idx >> 3, k4 = (idx & 7) * 4;
            cp16(Ab + m * 36 + k4, W + (size_t)(row0 + m) * CC + k0 + k4);
        }
        #pragma unroll
        for (int i = 0; i < 4; ++i) {                     // 32x128 x tile
            int idx = tid + i * 256, k = idx >> 5, n4 = (idx & 31) * 4;
            cp16(Bb + k * 136 + n4, xb + (size_t)(k0 + k) * LL + l0 + n4);
        }
        CP_COMMIT();
    };

    const int NIT = CC / 32;   // 16
    stage(0, 0); stage(1, 32);
    int ld = 2, cb = 0;
    for (int it = 0; it < NIT; ++it) {
        if (it < NIT - 2) { CP_WAIT(1); } else { CP_WAIT(0); }
        __syncthreads();
        if (it + 2 < NIT) { stage(ld, (it + 2) * 32); ld = (ld == 2) ? 0 : ld + 1; }
        const unsigned smAb = smA + (unsigned)(cb * QKV_AF) * 4;
        const float* Bb = Bs + cb * QKV_BF;
        cb = (cb == 2) ? 0 : cb + 1;
        #pragma unroll
        for (int ks = 0; ks < 4; ++ks) {
            const int kk = ks * 8;
            unsigned af[2][4], bf[4][2];
            #pragma unroll
            for (int mi = 0; mi < 2; ++mi)
                ldsm_x4(af[mi], smAb + (unsigned)((wm + mi * 16 + arow) * 36 + kk + acol) * 4);
            #pragma unroll
            for (int ni = 0; ni < 4; ++ni) {
                int nb = wn + ni * 8;
                bf[ni][0] = __float_as_uint(Bb[(kk + t    ) * 136 + nb + g]);
                bf[ni][1] = __float_as_uint(Bb[(kk + t + 4) * 136 + nb + g]);
            }
            #pragma unroll
            for (int mi = 0; mi < 2; ++mi)
                #pragma unroll
                for (int ni = 0; ni < 4; ++ni)
                    mma_tf32(acc[mi][ni], af[mi], bf[ni]);
        }
    }

    #pragma unroll
    for (int mi = 0; mi < 2; ++mi) {
        int r0r = row0 + wm + mi * 16 + g;
        int r1r = r0r + 8;
        float b0v = bias[r0r], b1v = bias[r1r];
        #pragma unroll
        for (int ni = 0; ni < 4; ++ni) {
            int col = l0 + wn + ni * 8 + 2 * t;
            *(float2*)&out[(size_t)r0r * LL + col] =
                make_float2(acc[mi][ni][0] + b0v, acc[mi][ni][1] + b0v);
            *(float2*)&out[(size_t)r1r * LL + col] =
                make_float2(acc[mi][ni][2] + b1v, acc[mi][ni][3] + b1v);
        }
    }
}

// ---------------------------------------------------------------------------
// Kernel 2: scores S = scale*(q^T k). Block 128q x 128k; CQ=64 staged as two
// cp.async groups. Both operands [c][n] -> scalar LDS (trans-LDSM unusable
// for 32-bit elements). Short kernel; unchanged from round 9 except no cvt.
// ---------------------------------------------------------------------------
#define SC_SMEM_FLOATS (2*64*136)
__global__ __launch_bounds__(256) void scores_kernel()
{
    extern __shared__ float sm[];
    float* Qs = sm;              // [64][136]
    float* Ks = sm + 64 * 136;

    const int b  = blockIdx.z;
    const int q0 = blockIdx.y * 128;
    const int k0 = blockIdx.x * 128;

    const int tid = threadIdx.x, w = tid >> 5, lane = tid & 31;
    const int g = lane >> 2, t = lane & 3;
    const int wm = (w >> 2) * 64, wn = (w & 3) * 32;
    const float* qb = g_q + (size_t)b * CQ * LL;
    const float* kb = g_k + (size_t)b * CQ * LL;

    auto stage = [&](int h) {
        int cbase = h * 32;
        #pragma unroll
        for (int i = 0; i < 4; ++i) {
            int idx = tid + i * 256, c = cbase + (idx >> 5), n4 = (idx & 31) * 4;
            cp16(Qs + c * 136 + n4, qb + (size_t)c * LL + q0 + n4);
            cp16(Ks + c * 136 + n4, kb + (size_t)c * LL + k0 + n4);
        }
        CP_COMMIT();
    };
    stage(0);
    stage(1);

    float acc[4][4][4] = {};

    #pragma unroll
    for (int h = 0; h < 2; ++h) {
        if (h == 0) { CP_WAIT(1); } else { CP_WAIT(0); }
        __syncthreads();
        #pragma unroll
        for (int ks = 0; ks < 4; ++ks) {
            const int kk = h * 32 + ks * 8;
            unsigned af[4][4], bf[4][2];
            #pragma unroll
            for (int mi = 0; mi < 4; ++mi) {
                int mb = wm + mi * 16;
                af[mi][0] = __float_as_uint(Qs[(kk + t    ) * 136 + mb + g    ]);
                af[mi][1] = __float_as_uint(Qs[(kk + t    ) * 136 + mb + g + 8]);
                af[mi][2] = __float_as_uint(Qs[(kk + t + 4) * 136 + mb + g    ]);
                af[mi][3] = __float_as_uint(Qs[(kk + t + 4) * 136 + mb + g + 8]);
            }
            #pragma unroll
            for (int ni = 0; ni < 4; ++ni) {
                int nb = wn + ni * 8;
                bf[ni][0] = __float_as_uint(Ks[(kk + t    ) * 136 + nb + g]);
                bf[ni][1] = __float_as_uint(Ks[(kk + t + 4) * 136 + nb + g]);
            }
            #pragma unroll
            for (int mi = 0; mi < 4; ++mi)
                #pragma unroll
                for (int ni = 0; ni < 4; ++ni)
                    mma_tf32(acc[mi][ni], af[mi], bf[ni]);
        }
    }

    float* sb = g_attn + (size_t)b * LL * LL;
    #pragma unroll
    for (int mi = 0; mi < 4; ++mi) {
        int r0r = q0 + wm + mi * 16 + g;
        int r1r = r0r + 8;
        #pragma unroll
        for (int ni = 0; ni < 4; ++ni) {
            int col = k0 + wn + ni * 8 + 2 * t;
            *(float2*)&sb[(size_t)r0r * LL + col] =
                make_float2(acc[mi][ni][0] * SCALE, acc[mi][ni][1] * SCALE);
            *(float2*)&sb[(size_t)r1r * LL + col] =
                make_float2(acc[mi][ni][2] * SCALE, acc[mi][ni][3] * SCALE);
        }
    }
}

// ---------------------------------------------------------------------------
// Kernel 3: row softmax, in place, float4 vectorized.
// ---------------------------------------------------------------------------
__global__ __launch_bounds__(256) void softmax_kernel()
{
    const int b = blockIdx.y, q = blockIdx.x;
    float4* row = reinterpret_cast<float4*>(g_attn + ((size_t)b * LL + q) * LL);
    const int tid = threadIdx.x;

    float4 u = row[tid], v = row[tid + 256];
    float m = fmaxf(fmaxf(fmaxf(u.x, u.y), fmaxf(u.z, u.w)),
                    fmaxf(fmaxf(v.x, v.y), fmaxf(v.z, v.w)));

    __shared__ float red[256];
    red[tid] = m; __syncthreads();
    #pragma unroll
    for (int s = 128; s > 0; s >>= 1) {
        if (tid < s) red[tid] = fmaxf(red[tid], red[tid + s]);
        __syncthreads();
    }
    m = red[0]; __syncthreads();

    u.x = __expf(u.x - m); u.y = __expf(u.y - m);
    u.z = __expf(u.z - m); u.w = __expf(u.w - m);
    v.x = __expf(v.x - m); v.y = __expf(v.y - m);
    v.z = __expf(v.z - m); v.w = __expf(v.w - m);
    float sum = (u.x + u.y + u.z + u.w) + (v.x + v.y + v.z + v.w);

    red[tid] = sum; __syncthreads();
    #pragma unroll
    for (int s = 128; s > 0; s >>= 1) {
        if (tid < s) red[tid] += red[tid + s];
        __syncthreads();
    }
    const float inv = 1.0f / red[0];

    u.x *= inv; u.y *= inv; u.z *= inv; u.w *= inv;
    v.x *= inv; v.y *= inv; v.z *= inv; v.w *= inv;
    row[tid] = u; row[tid + 256] = v;
}

// ---------------------------------------------------------------------------
// Kernel 4: PV: av[b,c,q] = sum_k v[b,c,k]*attn[b,q,k]. Block 128c x 128q,
// Kstep=32 over K=2048, 3-stage cp.async. Fully LDSM:
//   As[128][36] = v[c][k]     A-frag via ldmatrix.x4
//   Ps[128][36] = attn[q][k]  B-frag via ldmatrix.x2 (no transpose anywhere)
// ---------------------------------------------------------------------------
#define PV_STAGES 3
#define PV_TF (128*36)
#define PV_SMEM_FLOATS (PV_STAGES*2*PV_TF)
__global__ __launch_bounds__(256) void pv_kernel()
{
    extern __shared__ float sm[];
    float* As = sm;                      // [3][128][36]
    float* Ps = sm + PV_STAGES * PV_TF;  // [3][128][36]

    const int b  = blockIdx.z;
    const int c0 = blockIdx.y * 128;
    const int q0 = blockIdx.x * 128;

    const int tid = threadIdx.x, w = tid >> 5, lane = tid & 31;
    const int wm = (w >> 2) * 64, wn = (w & 3) * 32;
    const float* vb = g_v    + (size_t)b * CC * LL;
    const float* ab = g_attn + (size_t)b * LL * LL;

    // ldmatrix per-lane offsets
    const int arow = ((lane >> 3) & 1) * 8 + (lane & 7);   // A x4
    const int acol = (lane >> 4) * 4;
    const int brow = (lane & 7);                           // B x2
    const int bcol = ((lane >> 3) & 1) * 4;
    const unsigned smA = (unsigned)__cvta_generic_to_shared(As);
    const unsigned smP = (unsigned)__cvta_generic_to_shared(Ps);

    float acc[4][4][4] = {};

    auto stage = [&](int buf, int k0) {
        float* Ab = As + buf * PV_TF;
        float* Pb = Ps + buf * PV_TF;
        #pragma unroll
        for (int i = 0; i < 4; ++i) {
            int idx = tid + i * 256, m = idx >> 3, k4 = (idx & 7) * 4;
            cp16(Ab + m * 36 + k4, vb + (size_t)(c0 + m) * LL + k0 + k4);
            cp16(Pb + m * 36 + k4, ab + (size_t)(q0 + m) * LL + k0 + k4);
        }
        CP_COMMIT();
    };

    const int NIT = LL / 32;   // 64
    stage(0, 0); stage(1, 32);
    int ld = 2, cb = 0;
    for (int it = 0; it < NIT; ++it) {
        if (it < NIT - 2) { CP_WAIT(1); } else { CP_WAIT(0); }
        __syncthreads();
        if (it + 2 < NIT) { stage(ld, (it + 2) * 32); ld = (ld == 2) ? 0 : ld + 1; }
        const unsigned smAb = smA + (unsigned)(cb * PV_TF) * 4;
        const unsigned smPb = smP + (unsigned)(cb * PV_TF) * 4;
        cb = (cb == 2) ? 0 : cb + 1;
        #pragma unroll
        for (int ks = 0; ks < 4; ++ks) {
            const int kk = ks * 8;
            unsigned af[4][4], bf[4][2];
            #pragma unroll
            for (int mi = 0; mi < 4; ++mi)
                ldsm_x4(af[mi], smAb + (unsigned)((wm + mi * 16 + arow) * 36 + kk + acol) * 4);
            #pragma unroll
            for (int ni = 0; ni < 4; ++ni)
                ldsm_x2(bf[ni], smPb + (unsigned)((wn + ni * 8 + brow) * 36 + kk + bcol) * 4);
            #pragma unroll
            for (int mi = 0; mi < 4; ++mi)
                #pragma unroll
                for (int ni = 0; ni < 4; ++ni)
                    mma_tf32(acc[mi][ni], af[mi], bf[ni]);
        }
    }

    const int g = lane >> 2, t = lane & 3;
    float* ob = g_av + (size_t)b * CC * LL;
    #pragma unroll
    for (int mi = 0; mi < 4; ++mi) {
        int r0r = c0 + wm + mi * 16 + g;
        int r1r = r0r + 8;
        #pragma unroll
        for (int ni = 0; ni < 4; ++ni) {
            int col = q0 + wn + ni * 8 + 2 * t;
            *(float2*)&ob[(size_t)r0r * LL + col] =
                make_float2(acc[mi][ni][0], acc[mi][ni][1]);
            *(float2*)&ob[(size_t)r1r * LL + col] =
                make_float2(acc[mi][ni][2], acc[mi][ni][3]);
        }
    }
}

// ---------------------------------------------------------------------------
// Kernel 5: O projection + bias + residual. Block 128o x 128l, Kstep=32,
// 3-stage cp.async. A (Wo) via LDSM x4; B (av, [k][n]) scalar LDS.
// ---------------------------------------------------------------------------
#define OP_STAGES 3
#define OP_AF (128*36)
#define OP_BF (32*136)
#define OP_SMEM_FLOATS (OP_STAGES*(OP_AF+OP_BF))
__global__ __launch_bounds__(256) void outproj_kernel(
    const float* __restrict__ x,
    const float* __restrict__ Wo, const float* __restrict__ bo,
    float* __restrict__ out)
{
    extern __shared__ float sm[];
    float* As = sm;                      // [3][128][36]  Wo tile
    float* Bs = sm + OP_STAGES * OP_AF;  // [3][32][136]  av tile

    const int b  = blockIdx.z;
    const int r0 = blockIdx.y * 128;
    const int l0 = blockIdx.x * 128;

    const int tid = threadIdx.x, w = tid >> 5, lane = tid & 31;
    const int g = lane >> 2, t = lane & 3;
    const int wm = (w >> 2) * 64, wn = (w & 3) * 32;
    const float* avb = g_av + (size_t)b * CC * LL;

    const int arow = ((lane >> 3) & 1) * 8 + (lane & 7);
    const int acol = (lane >> 4) * 4;
    const unsigned smA = (unsigned)__cvta_generic_to_shared(As);

    float acc[4][4][4] = {};

    auto stage = [&](int buf, int k0) {
        float* Ab = As + buf * OP_AF;
        float* Bb = Bs + buf * OP_BF;
        #pragma unroll
        for (int i = 0; i < 4; ++i) {
            int idx = tid + i * 256, m = idx >> 3, k4 = (idx & 7) * 4;
            cp16(Ab + m * 36 + k4, Wo + (size_t)(r0 + m) * CC + k0 + k4);
        }
        #pragma unroll
        for (int i = 0; i < 4; ++i) {
            int idx = tid + i * 256, k = idx >> 5, n4 = (idx & 31) * 4;
            cp16(Bb + k * 136 + n4, avb + (size_t)(k0 + k) * LL + l0 + n4);
        }
        CP_COMMIT();
    };

    const int NIT = CC / 32;   // 16
    stage(0, 0); stage(1, 32);
    int ld = 2, cb = 0;
    for (int it = 0; it < NIT; ++it) {
        if (it < NIT - 2) { CP_WAIT(1); } else { CP_WAIT(0); }
        __syncthreads();
        if (it + 2 < NIT) { stage(ld, (it + 2) * 32); ld = (ld == 2) ? 0 : ld + 1; }
        const unsigned smAb = smA + (unsigned)(cb * OP_AF) * 4;
        const float* Bb = Bs + cb * OP_BF;
        cb = (cb == 2) ? 0 : cb + 1;
        #pragma unroll
        for (int ks = 0; ks < 4; ++ks) {
            const int kk = ks * 8;
            unsigned af[4][4], bf[4][2];
            #pragma unroll
            for (int mi = 0; mi < 4; ++mi)
                ldsm_x4(af[mi], smAb + (unsigned)((wm + mi * 16 + arow) * 36 + kk + acol) * 4);
            #pragma unroll
            for (int ni = 0; ni < 4; ++ni) {
                int nb = wn + ni * 8;
                bf[ni][0] = __float_as_uint(Bb[(kk + t    ) * 136 + nb + g]);
                bf[ni][1] = __float_as_uint(Bb[(kk + t + 4) * 136 + nb + g]);
            }
            #pragma unroll
            for (int mi = 0; mi < 4; ++mi)
                #pragma unroll
                for (int ni = 0; ni < 4; ++ni)
                    mma_tf32(acc[mi][ni], af[mi], bf[ni]);
        }
    }

    #pragma unroll
    for (int mi = 0; mi < 4; ++mi) {
        int ch0 = r0 + wm + mi * 16 + g;
        int ch1 = ch0 + 8;
        float b0v = bo[ch0], b1v = bo[ch1];
        #pragma unroll
        for (int ni = 0; ni < 4; ++ni) {
            int col = l0 + wn + ni * 8 + 2 * t;
            size_t off0 = (size_t)b * CC * LL + (size_t)ch0 * LL + col;
            size_t off1 = (size_t)b * CC * LL + (size_t)ch1 * LL + col;
            float2 x0 = *(const float2*)&x[off0];
            float2 x1 = *(const float2*)&x[off1];
            *(float2*)&out[off0] = make_float2(acc[mi][ni][0] + b0v + x0.x,
                                               acc[mi][ni][1] + b0v + x0.y);
            *(float2*)&out[off1] = make_float2(acc[mi][ni][2] + b1v + x1.x,
                                               acc[mi][ni][3] + b1v + x1.y);
        }
    }
}

// ---------------------------------------------------------------------------
// Launch: 5 kernels on one stream, graph-capturable, no allocations.
// ---------------------------------------------------------------------------
extern "C" void kernel_launch(void* const* d_in, const int* in_sizes, int n_in,
                              void* d_out, int out_size)
{
    (void)in_sizes; (void)n_in; (void)out_size;
    const float* x  = (const float*)d_in[0];
    const float* Wq = (const float*)d_in[1];
    const float* bq = (const float*)d_in[2];
    const float* Wk = (const float*)d_in[3];
    const float* bk = (const float*)d_in[4];
    const float* Wv = (const float*)d_in[5];
    const float* bv = (const float*)d_in[6];
    const float* Wo = (const float*)d_in[7];
    const float* bo = (const float*)d_in[8];
    float* out = (float*)d_out;

    const int qkv_sm = QKV_SMEM_FLOATS * 4;   // 79872 B
    const int sc_sm  = SC_SMEM_FLOATS  * 4;   // 69632 B
    const int pv_sm  = PV_SMEM_FLOATS  * 4;   // 110592 B
    const int op_sm  = OP_SMEM_FLOATS  * 4;   // 107520 B

    cudaFuncSetAttribute(qkv_kernel,     cudaFuncAttributeMaxDynamicSharedMemorySize, qkv_sm);
    cudaFuncSetAttribute(scores_kernel,  cudaFuncAttributeMaxDynamicSharedMemorySize, sc_sm);
    cudaFuncSetAttribute(pv_kernel,      cudaFuncAttributeMaxDynamicSharedMemorySize, pv_sm);
    cudaFuncSetAttribute(outproj_kernel, cudaFuncAttributeMaxDynamicSharedMemorySize, op_sm);

    dim3 blk(256);
    qkv_kernel    <<<dim3(LL / 128, 10,        BB), blk, qkv_sm>>>(x, Wq, bq, Wk, bk, Wv, bv);
    scores_kernel <<<dim3(LL / 128, LL / 128,  BB), blk, sc_sm>>>();
    softmax_kernel<<<dim3(LL,       BB           ), blk>>>();
    pv_kernel     <<<dim3(LL / 128, CC / 128,  BB), blk, pv_sm>>>();
    outproj_kernel<<<dim3(LL / 128, CC / 128,  BB), blk, op_sm>>>(x, Wo, bo, out);
}

// round 11
// speedup vs baseline: 6.4352x; 1.5202x over previous
#include <cuda_runtime.h>
#include <cuda_bf16.h>

// Shapes (fixed by the problem)
#define BB  8
#define CC  512
#define LL  2048
#define CQ  64
#define SCALE 0.125f   // CQK^-0.5

typedef __nv_bfloat16  bf16;
typedef __nv_bfloat162 bf162;

// ---------------------------------------------------------------------------
// Scratch (static __device__ arrays — no allocation anywhere)
// ---------------------------------------------------------------------------
__device__ bf16  g_xb[(size_t)BB * CC * LL];        // 16.8 MB  x in bf16
__device__ bf16  g_wq[CQ * CC], g_wk[CQ * CC];      // 64 KB each
__device__ bf16  g_wv[(size_t)CC * CC];             // 512 KB
__device__ bf16  g_wo[(size_t)CC * CC];             // 512 KB
__device__ bf16  g_qb[(size_t)BB * CQ * LL];        // 2 MB
__device__ bf16  g_kb[(size_t)BB * CQ * LL];        // 2 MB
__device__ bf16  g_vb[(size_t)BB * CC * LL];        // 16.8 MB
__device__ float g_scores[(size_t)BB * LL * LL];    // 134 MB (fp32 pre-softmax)
__device__ bf16  g_attnb[(size_t)BB * LL * LL];     // 67 MB  (bf16 post-softmax)
__device__ bf16  g_avb[(size_t)BB * CC * LL];       // 16.8 MB

// ---------------------------------------------------------------------------
// Helpers
// ---------------------------------------------------------------------------
__device__ __forceinline__ void cp16(void* dst_smem, const void* src) {
    unsigned d = (unsigned)__cvta_generic_to_shared(dst_smem);
    asm volatile("cp.async.cg.shared.global [%0], [%1], 16;" :: "r"(d), "l"(src));
}
#define CP_COMMIT() asm volatile("cp.async.commit_group;")
#define CP_WAIT(N)  asm volatile("cp.async.wait_group " #N ";")

__device__ __forceinline__ void ldsm_x4(unsigned* r, unsigned s) {
    asm volatile("ldmatrix.sync.aligned.m8n8.x4.shared.b16 {%0,%1,%2,%3}, [%4];"
        : "=r"(r[0]), "=r"(r[1]), "=r"(r[2]), "=r"(r[3]) : "r"(s));
}
__device__ __forceinline__ void ldsm_x2(unsigned* r, unsigned s) {
    asm volatile("ldmatrix.sync.aligned.m8n8.x2.shared.b16 {%0,%1}, [%2];"
        : "=r"(r[0]), "=r"(r[1]) : "r"(s));
}
__device__ __forceinline__ void ldsm_x4t(unsigned* r, unsigned s) {
    asm volatile("ldmatrix.sync.aligned.m8n8.x4.trans.shared.b16 {%0,%1,%2,%3}, [%4];"
        : "=r"(r[0]), "=r"(r[1]), "=r"(r[2]), "=r"(r[3]) : "r"(s));
}
__device__ __forceinline__ void ldsm_x2t(unsigned* r, unsigned s) {
    asm volatile("ldmatrix.sync.aligned.m8n8.x2.trans.shared.b16 {%0,%1}, [%2];"
        : "=r"(r[0]), "=r"(r[1]) : "r"(s));
}

// D += A(16x16 row) * B(16x8 col), fp32 accum.
__device__ __forceinline__ void mma_bf16(float* c, const unsigned* a, const unsigned* b) {
    asm volatile(
        "mma.sync.aligned.m16n8k16.row.col.f32.bf16.bf16.f32 "
        "{%0,%1,%2,%3}, {%4,%5,%6,%7}, {%8,%9}, {%0,%1,%2,%3};"
        : "+f"(c[0]), "+f"(c[1]), "+f"(c[2]), "+f"(c[3])
        : "r"(a[0]), "r"(a[1]), "r"(a[2]), "r"(a[3]), "r"(b[0]), "r"(b[1]));
}
// Frag maps (lane = 4g+t):
//  A: a0=A[g][2t,2t+1] a1=A[g+8][2t..] a2=A[g][8+2t..] a3=A[g+8][8+2t..]
//  B: b0=B[2t,2t+1][g] b1=B[8+2t..][g]   (B indexed [k][n])
//  C: c0=C[g][2t] c1=C[g][2t+1] c2=C[g+8][2t] c3=C[g+8][2t+1]
// Smem layouts & conflict math:
//  [m][k] tiles, row stride 40 bf16 = 5×16B units → 5r mod 8 distinct (LDSM-safe)
//  [k][n] tiles, row stride 136 bf16 = 17 units  → r  mod 8 distinct (LDSM-safe)

// ---------------------------------------------------------------------------
// Kernel 0: fp32 -> bf16 conversion of x and weights (once per launch, ~9M elems)
// ---------------------------------------------------------------------------
#define NX  ((size_t)BB * CC * LL)
#define NWQ ((size_t)CQ * CC)
#define NWV ((size_t)CC * CC)
#define CVT_PAIRS ((NX + 2 * NWQ + 2 * NWV) / 2)
__global__ __launch_bounds__(256) void cvt_kernel(
    const float* __restrict__ x,  const float* __restrict__ Wq,
    const float* __restrict__ Wk, const float* __restrict__ Wv,
    const float* __restrict__ Wo)
{
    size_t i = ((size_t)blockIdx.x * 256 + threadIdx.x) * 2;
    if (i < NX) {
        *(bf162*)&g_xb[i] = __float22bfloat162_rn(*(const float2*)&x[i]); return;
    }
    i -= NX;
    if (i < NWQ) { *(bf162*)&g_wq[i] = __float22bfloat162_rn(*(const float2*)&Wq[i]); return; }
    i -= NWQ;
    if (i < NWQ) { *(bf162*)&g_wk[i] = __float22bfloat162_rn(*(const float2*)&Wk[i]); return; }
    i -= NWQ;
    if (i < NWV) { *(bf162*)&g_wv[i] = __float22bfloat162_rn(*(const float2*)&Wv[i]); return; }
    i -= NWV;
    if (i < NWV) { *(bf162*)&g_wo[i] = __float22bfloat162_rn(*(const float2*)&Wo[i]); }
}

// ---------------------------------------------------------------------------
// Kernel 1: fused QKV projection (bf16 mma). Block M=64 x N=128, Kchunk=32
// (2 k16 steps), 3-stage cp.async. Warps 2(M)x4(N), warp 32x32.
//   Ws[64][40]  (W, [m][k])   A via ldsm_x4
//   Bs[32][136] (x, [k][n])   B via ldsm_x2t
// ---------------------------------------------------------------------------
#define QKV_A (64 * 40)
#define QKV_B (32 * 136)
#define QKV_STAGES 3
#define QKV_SMEM ((QKV_STAGES * (QKV_A + QKV_B)) * 2)
__global__ __launch_bounds__(256) void qkv_kernel(
    const float* __restrict__ bq, const float* __restrict__ bk,
    const float* __restrict__ bv)
{
    extern __shared__ bf16 sm[];
    bf16* As = sm;
    bf16* Bs = sm + QKV_STAGES * QKV_A;

    const int b  = blockIdx.z;
    const int rt = blockIdx.y;           // 0..9
    const int l0 = blockIdx.x * 128;

    const bf16* W; const float* bias; bf16* out; int row0;
    if (rt == 0)      { W = g_wq; bias = bq; out = g_qb + (size_t)b * CQ * LL; row0 = 0; }
    else if (rt == 1) { W = g_wk; bias = bk; out = g_kb + (size_t)b * CQ * LL; row0 = 0; }
    else              { W = g_wv; bias = bv; out = g_vb + (size_t)b * CC * LL; row0 = (rt - 2) * 64; }

    const int tid = threadIdx.x, w = tid >> 5, lane = tid & 31;
    const int g = lane >> 2, t = lane & 3;
    const int wm = (w >> 2) * 32, wn = (w & 3) * 32;
    const int l15 = lane & 15, hi = lane >> 4;
    const bf16* xb = g_xb + (size_t)b * CC * LL;
    const unsigned smA = (unsigned)__cvta_generic_to_shared(As);
    const unsigned smB = (unsigned)__cvta_generic_to_shared(Bs);

    float acc[2][4][4] = {};

    auto stage = [&](int buf, int k0) {
        bf16* Ab = As + buf * QKV_A;
        bf16* Bb = Bs + buf * QKV_B;
        {   // 64x32 W tile: 256 chunks of 8 bf16
            int m = tid >> 2, k8 = (tid & 3) * 8;
            cp16(Ab + m * 40 + k8, W + (size_t)(row0 + m) * CC + k0 + k8);
        }
        #pragma unroll
        for (int i = 0; i < 2; ++i) {   // 32x128 x tile: 512 chunks
            int idx = tid + i * 256, k = idx >> 4, n8 = (idx & 15) * 8;
            cp16(Bb + k * 136 + n8, xb + (size_t)(k0 + k) * LL + l0 + n8);
        }
        CP_COMMIT();
    };

    const int NIT = CC / 32;   // 16
    stage(0, 0); stage(1, 32);
    int ld = 2, cb = 0;
    for (int it = 0; it < NIT; ++it) {
        if (it < NIT - 2) { CP_WAIT(1); } else { CP_WAIT(0); }
        __syncthreads();
        if (it + 2 < NIT) { stage(ld, (it + 2) * 32); ld = (ld == 2) ? 0 : ld + 1; }
        const unsigned a0 = smA + (unsigned)(cb * QKV_A) * 2;
        const unsigned b0a = smB + (unsigned)(cb * QKV_B) * 2;
        cb = (cb == 2) ? 0 : cb + 1;
        #pragma unroll
        for (int ks = 0; ks < 2; ++ks) {
            const int kk = ks * 16;
            unsigned af[2][4], bf[4][2];
            #pragma unroll
            for (int mi = 0; mi < 2; ++mi)
                ldsm_x4(af[mi], a0 + (unsigned)((wm + mi * 16 + l15) * 40 + kk) * 2 + hi * 16);
            #pragma unroll
            for (int ni = 0; ni < 4; ++ni)
                ldsm_x2t(bf[ni], b0a + (unsigned)((kk + l15) * 136 + wn + ni * 8) * 2);
            #pragma unroll
            for (int mi = 0; mi < 2; ++mi)
                #pragma unroll
                for (int ni = 0; ni < 4; ++ni)
                    mma_bf16(acc[mi][ni], af[mi], bf[ni]);
        }
    }

    #pragma unroll
    for (int mi = 0; mi < 2; ++mi) {
        int r0r = row0 + wm + mi * 16 + g;
        int r1r = r0r + 8;
        float b0v = bias[r0r], b1v = bias[r1r];
        #pragma unroll
        for (int ni = 0; ni < 4; ++ni) {
            int col = l0 + wn + ni * 8 + 2 * t;
            *(bf162*)&out[(size_t)r0r * LL + col] =
                __floats2bfloat162_rn(acc[mi][ni][0] + b0v, acc[mi][ni][1] + b0v);
            *(bf162*)&out[(size_t)r1r * LL + col] =
                __floats2bfloat162_rn(acc[mi][ni][2] + b1v, acc[mi][ni][3] + b1v);
        }
    }
}

// ---------------------------------------------------------------------------
// Kernel 2: scores = scale*(q^T k), fp32 out. Block 128q x 128k, CQ=64 =
// 4 k16 steps, staged as two cp.async halves. Warps 2x4, warp 64q x 32k.
//   Qs/Ks [64][136] ([c][n])   A via ldsm_x4t, B via ldsm_x2t
// ---------------------------------------------------------------------------
#define SC_SMEM (2 * 64 * 136 * 2)
__global__ __launch_bounds__(256) void scores_kernel()
{
    extern __shared__ bf16 sm[];
    bf16* Qs = sm;
    bf16* Ks = sm + 64 * 136;

    const int b  = blockIdx.z;
    const int q0 = blockIdx.y * 128;
    const int k0 = blockIdx.x * 128;

    const int tid = threadIdx.x, w = tid >> 5, lane = tid & 31;
    const int g = lane >> 2, t = lane & 3;
    const int wm = (w >> 2) * 64, wn = (w & 3) * 32;
    const int l15 = lane & 15;
    const bf16* qb = g_qb + (size_t)b * CQ * LL;
    const bf16* kb = g_kb + (size_t)b * CQ * LL;
    const unsigned smQ = (unsigned)__cvta_generic_to_shared(Qs);
    const unsigned smK = (unsigned)__cvta_generic_to_shared(Ks);

    auto stage = [&](int h) {
        int cbase = h * 32;
        #pragma unroll
        for (int i = 0; i < 2; ++i) {
            int idx = tid + i * 256, c = cbase + (idx >> 4), n8 = (idx & 15) * 8;
            cp16(Qs + c * 136 + n8, qb + (size_t)c * LL + q0 + n8);
            cp16(Ks + c * 136 + n8, kb + (size_t)c * LL + k0 + n8);
        }
        CP_COMMIT();
    };
    stage(0);
    stage(1);

    float acc[4][4][4] = {};

    #pragma unroll
    for (int h = 0; h < 2; ++h) {
        if (h == 0) { CP_WAIT(1); } else { CP_WAIT(0); }
        __syncthreads();
        #pragma unroll
        for (int ks = 0; ks < 2; ++ks) {
            const int kk = h * 32 + ks * 16;
            unsigned af[4][4], bf[4][2];
            #pragma unroll
            for (int mi = 0; mi < 4; ++mi)
                ldsm_x4t(af[mi], smQ +
                    (unsigned)((kk + (lane >> 4) * 8 + (lane & 7)) * 136
                               + wm + mi * 16 + ((lane >> 3) & 1) * 8) * 2);
            #pragma unroll
            for (int ni = 0; ni < 4; ++ni)
                ldsm_x2t(bf[ni], smK + (unsigned)((kk + l15) * 136 + wn + ni * 8) * 2);
            #pragma unroll
            for (int mi = 0; mi < 4; ++mi)
                #pragma unroll
                for (int ni = 0; ni < 4; ++ni)
                    mma_bf16(acc[mi][ni], af[mi], bf[ni]);
        }
    }

    float* sb = g_scores + (size_t)b * LL * LL;
    #pragma unroll
    for (int mi = 0; mi < 4; ++mi) {
        int r0r = q0 + wm + mi * 16 + g;
        int r1r = r0r + 8;
        #pragma unroll
        for (int ni = 0; ni < 4; ++ni) {
            int col = k0 + wn + ni * 8 + 2 * t;
            *(float2*)&sb[(size_t)r0r * LL + col] =
                make_float2(acc[mi][ni][0] * SCALE, acc[mi][ni][1] * SCALE);
            *(float2*)&sb[(size_t)r1r * LL + col] =
                make_float2(acc[mi][ni][2] * SCALE, acc[mi][ni][3] * SCALE);
        }
    }
}

// ---------------------------------------------------------------------------
// Kernel 3: row softmax. Reads fp32 scores, writes bf16 attn (half traffic).
// ---------------------------------------------------------------------------
__global__ __launch_bounds__(256) void softmax_kernel()
{
    const int b = blockIdx.y, q = blockIdx.x;
    const float4* row = reinterpret_cast<const float4*>(g_scores + ((size_t)b * LL + q) * LL);
    bf16* orow = g_attnb + ((size_t)b * LL + q) * LL;
    const int tid = threadIdx.x;

    float4 u = row[tid], v = row[tid + 256];
    float m = fmaxf(fmaxf(fmaxf(u.x, u.y), fmaxf(u.z, u.w)),
                    fmaxf(fmaxf(v.x, v.y), fmaxf(v.z, v.w)));

    __shared__ float red[256];
    red[tid] = m; __syncthreads();
    #pragma unroll
    for (int s = 128; s > 0; s >>= 1) {
        if (tid < s) red[tid] = fmaxf(red[tid], red[tid + s]);
        __syncthreads();
    }
    m = red[0]; __syncthreads();

    u.x = __expf(u.x - m); u.y = __expf(u.y - m);
    u.z = __expf(u.z - m); u.w = __expf(u.w - m);
    v.x = __expf(v.x - m); v.y = __expf(v.y - m);
    v.z = __expf(v.z - m); v.w = __expf(v.w - m);
    float sum = (u.x + u.y + u.z + u.w) + (v.x + v.y + v.z + v.w);

    red[tid] = sum; __syncthreads();
    #pragma unroll
    for (int s = 128; s > 0; s >>= 1) {
        if (tid < s) red[tid] += red[tid + s];
        __syncthreads();
    }
    const float inv = 1.0f / red[0];

    *(bf162*)&orow[4 * tid]        = __floats2bfloat162_rn(u.x * inv, u.y * inv);
    *(bf162*)&orow[4 * tid + 2]    = __floats2bfloat162_rn(u.z * inv, u.w * inv);
    *(bf162*)&orow[1024 + 4 * tid] = __floats2bfloat162_rn(v.x * inv, v.y * inv);
    *(bf162*)&orow[1026 + 4 * tid] = __floats2bfloat162_rn(v.z * inv, v.w * inv);
}

// ---------------------------------------------------------------------------
// Kernel 4: PV: av[b,c,q] = sum_k v[b,c,k]*attn[b,q,k]. Block 128c x 128q,
// Kchunk=32 (2 k16 steps) over K=2048, 3-stage cp.async. Fully ldmatrix:
//   As[128][40] = v[c][k]     A via ldsm_x4
//   Ps[128][40] = attn[q][k]  B via ldsm_x2 (non-trans; [n][k] storage gives
//                             b0 = attn[q0+g][k+2t] = B[k][n] map directly)
// ---------------------------------------------------------------------------
#define PV_T (128 * 40)
#define PV_STAGES 3
#define PV_SMEM (PV_STAGES * 2 * PV_T * 2)
__global__ __launch_bounds__(256) void pv_kernel()
{
    extern __shared__ bf16 sm[];
    bf16* As = sm;
    bf16* Ps = sm + PV_STAGES * PV_T;

    const int b  = blockIdx.z;
    const int c0 = blockIdx.y * 128;
    const int q0 = blockIdx.x * 128;

    const int tid = threadIdx.x, w = tid >> 5, lane = tid & 31;
    const int wm = (w >> 2) * 64, wn = (w & 3) * 32;
    const int l15 = lane & 15, hi = lane >> 4;
    const int l7 = lane & 7, b8 = ((lane >> 3) & 1) * 8;
    const bf16* vb = g_vb    + (size_t)b * CC * LL;
    const bf16* ab = g_attnb + (size_t)b * LL * LL;
    const unsigned smA = (unsigned)__cvta_generic_to_shared(As);
    const unsigned smP = (unsigned)__cvta_generic_to_shared(Ps);

    float acc[4][4][4] = {};

    auto stage = [&](int buf, int k0) {
        bf16* Ab = As + buf * PV_T;
        bf16* Pb = Ps + buf * PV_T;
        #pragma unroll
        for (int i = 0; i < 2; ++i) {   // 128x32 tiles: 512 chunks each
            int idx = tid + i * 256, m = idx >> 2, k8 = (idx & 3) * 8;
            cp16(Ab + m * 40 + k8, vb + (size_t)(c0 + m) * LL + k0 + k8);
            cp16(Pb + m * 40 + k8, ab + (size_t)(q0 + m) * LL + k0 + k8);
        }
        CP_COMMIT();
    };

    const int NIT = LL / 32;   // 64
    stage(0, 0); stage(1, 32);
    int ld = 2, cb = 0;
    for (int it = 0; it < NIT; ++it) {
        if (it < NIT - 2) { CP_WAIT(1); } else { CP_WAIT(0); }
        __syncthreads();
        if (it + 2 < NIT) { stage(ld, (it + 2) * 32); ld = (ld == 2) ? 0 : ld + 1; }
        const unsigned a0 = smA + (unsigned)(cb * PV_T) * 2;
        const unsigned p0 = smP + (unsigned)(cb * PV_T) * 2;
        cb = (cb == 2) ? 0 : cb + 1;
        #pragma unroll
        for (int ks = 0; ks < 2; ++ks) {
            const int kk = ks * 16;
            unsigned af[4][4], bf[4][2];
            #pragma unroll
            for (int mi = 0; mi < 4; ++mi)
                ldsm_x4(af[mi], a0 + (unsigned)((wm + mi * 16 + l15) * 40 + kk) * 2 + hi * 16);
            #pragma unroll
            for (int ni = 0; ni < 4; ++ni)
                ldsm_x2(bf[ni], p0 + (unsigned)((wn + ni * 8 + l7) * 40 + kk + b8) * 2);
            #pragma unroll
            for (int mi = 0; mi < 4; ++mi)
                #pragma unroll
                for (int ni = 0; ni < 4; ++ni)
                    mma_bf16(acc[mi][ni], af[mi], bf[ni]);
        }
    }

    const int g = lane >> 2, t = lane & 3;
    bf16* ob = g_avb + (size_t)b * CC * LL;
    #pragma unroll
    for (int mi = 0; mi < 4; ++mi) {
        int r0r = c0 + wm + mi * 16 + g;
        int r1r = r0r + 8;
        #pragma unroll
        for (int ni = 0; ni < 4; ++ni) {
            int col = q0 + wn + ni * 8 + 2 * t;
            *(bf162*)&ob[(size_t)r0r * LL + col] =
                __floats2bfloat162_rn(acc[mi][ni][0], acc[mi][ni][1]);
            *(bf162*)&ob[(size_t)r1r * LL + col] =
                __floats2bfloat162_rn(acc[mi][ni][2], acc[mi][ni][3]);
        }
    }
}

// ---------------------------------------------------------------------------
// Kernel 5: O projection + bias + residual (fp32 out). Block 128o x 128l,
// Kchunk=32 over C=512, 3-stage cp.async.
//   Ws[128][40] (Wo, [m][k])  A via ldsm_x4
//   Bs[32][136] (av, [k][n])  B via ldsm_x2t
// ---------------------------------------------------------------------------
#define OP_A (128 * 40)
#define OP_B (32 * 136)
#define OP_STAGES 3
#define OP_SMEM ((OP_STAGES * (OP_A + OP_B)) * 2)
__global__ __launch_bounds__(256) void outproj_kernel(
    const float* __restrict__ x,
    const float* __restrict__ bo, float* __restrict__ out)
{
    extern __shared__ bf16 sm[];
    bf16* As = sm;
    bf16* Bs = sm + OP_STAGES * OP_A;

    const int b  = blockIdx.z;
    const int r0 = blockIdx.y * 128;
    const int l0 = blockIdx.x * 128;

    const int tid = threadIdx.x, w = tid >> 5, lane = tid & 31;
    const int g = lane >> 2, t = lane & 3;
    const int wm = (w >> 2) * 64, wn = (w & 3) * 32;
    const int l15 = lane & 15, hi = lane >> 4;
    const bf16* avb = g_avb + (size_t)b * CC * LL;
    const unsigned smA = (unsigned)__cvta_generic_to_shared(As);
    const unsigned smB = (unsigned)__cvta_generic_to_shared(Bs);

    float acc[4][4][4] = {};

    auto stage = [&](int buf, int k0) {
        bf16* Ab = As + buf * OP_A;
        bf16* Bb = Bs + buf * OP_B;
        #pragma unroll
        for (int i = 0; i < 2; ++i) {   // 128x32 Wo tile: 512 chunks
            int idx = tid + i * 256, m = idx >> 2, k8 = (idx & 3) * 8;
            cp16(Ab + m * 40 + k8, g_wo + (size_t)(r0 + m) * CC + k0 + k8);
        }
        #pragma unroll
        for (int i = 0; i < 2; ++i) {   // 32x128 av tile: 512 chunks
            int idx = tid + i * 256, k = idx >> 4, n8 = (idx & 15) * 8;
            cp16(Bb + k * 136 + n8, avb + (size_t)(k0 + k) * LL + l0 + n8);
        }
        CP_COMMIT();
    };

    const int NIT = CC / 32;   // 16
    stage(0, 0); stage(1, 32);
    int ld = 2, cb = 0;
    for (int it = 0; it < NIT; ++it) {
        if (it < NIT - 2) { CP_WAIT(1); } else { CP_WAIT(0); }
        __syncthreads();
        if (it + 2 < NIT) { stage(ld, (it + 2) * 32); ld = (ld == 2) ? 0 : ld + 1; }
        const unsigned a0 = smA + (unsigned)(cb * OP_A) * 2;
        const unsigned b0a = smB + (unsigned)(cb * OP_B) * 2;
        cb = (cb == 2) ? 0 : cb + 1;
        #pragma unroll
        for (int ks = 0; ks < 2; ++ks) {
            const int kk = ks * 16;
            unsigned af[4][4], bf[4][2];
            #pragma unroll
            for (int mi = 0; mi < 4; ++mi)
                ldsm_x4(af[mi], a0 + (unsigned)((wm + mi * 16 + l15) * 40 + kk) * 2 + hi * 16);
            #pragma unroll
            for (int ni = 0; ni < 4; ++ni)
                ldsm_x2t(bf[ni], b0a + (unsigned)((kk + l15) * 136 + wn + ni * 8) * 2);
            #pragma unroll
            for (int mi = 0; mi < 4; ++mi)
                #pragma unroll
                for (int ni = 0; ni < 4; ++ni)
                    mma_bf16(acc[mi][ni], af[mi], bf[ni]);
        }
    }

    #pragma unroll
    for (int mi = 0; mi < 4; ++mi) {
        int ch0 = r0 + wm + mi * 16 + g;
        int ch1 = ch0 + 8;
        float b0v = bo[ch0], b1v = bo[ch1];
        #pragma unroll
        for (int ni = 0; ni < 4; ++ni) {
            int col = l0 + wn + ni * 8 + 2 * t;
            size_t off0 = (size_t)b * CC * LL + (size_t)ch0 * LL + col;
            size_t off1 = (size_t)b * CC * LL + (size_t)ch1 * LL + col;
            float2 x0 = *(const float2*)&x[off0];
            float2 x1 = *(const float2*)&x[off1];
            *(float2*)&out[off0] = make_float2(acc[mi][ni][0] + b0v + x0.x,
                                               acc[mi][ni][1] + b0v + x0.y);
            *(float2*)&out[off1] = make_float2(acc[mi][ni][2] + b1v + x1.x,
                                               acc[mi][ni][3] + b1v + x1.y);
        }
    }
}

// ---------------------------------------------------------------------------
// Launch: 6 kernels on one stream, graph-capturable, no allocations.
// ---------------------------------------------------------------------------
extern "C" void kernel_launch(void* const* d_in, const int* in_sizes, int n_in,
                              void* d_out, int out_size)
{
    (void)in_sizes; (void)n_in; (void)out_size;
    const float* x  = (const float*)d_in[0];
    const float* Wq = (const float*)d_in[1];
    const float* bq = (const float*)d_in[2];
    const float* Wk = (const float*)d_in[3];
    const float* bk = (const float*)d_in[4];
    const float* Wv = (const float*)d_in[5];
    const float* bv = (const float*)d_in[6];
    const float* Wo = (const float*)d_in[7];
    const float* bo = (const float*)d_in[8];
    float* out = (float*)d_out;

    cudaFuncSetAttribute(pv_kernel,      cudaFuncAttributeMaxDynamicSharedMemorySize, PV_SMEM);
    cudaFuncSetAttribute(outproj_kernel, cudaFuncAttributeMaxDynamicSharedMemorySize, OP_SMEM);

    dim3 blk(256);
    cvt_kernel    <<<(unsigned)((CVT_PAIRS + 255) / 256), blk>>>(x, Wq, Wk, Wv, Wo);
    qkv_kernel    <<<dim3(LL / 128, 10,        BB), blk, QKV_SMEM>>>(bq, bk, bv);
    scores_kernel <<<dim3(LL / 128, LL / 128,  BB), blk, SC_SMEM>>>();
    softmax_kernel<<<dim3(LL,       BB           ), blk>>>();
    pv_kernel     <<<dim3(LL / 128, CC / 128,  BB), blk, PV_SMEM>>>();
    outproj_kernel<<<dim3(LL / 128, CC / 128,  BB), blk, OP_SMEM>>>(x, bo, out);
}

// round 12
// speedup vs baseline: 6.9578x; 1.0812x over previous
#include <cuda_runtime.h>
#include <cuda_bf16.h>

// Shapes (fixed by the problem)
#define BB  8
#define CC  512
#define LL  2048
#define CQ  64
#define SCALE 0.125f   // CQK^-0.5 (exact power of 2; folded into q at qkv epilogue)

typedef __nv_bfloat16  bf16;
typedef __nv_bfloat162 bf162;

// ---------------------------------------------------------------------------
// Scratch (static __device__ arrays — no allocation anywhere)
// ---------------------------------------------------------------------------
__device__ bf16 g_xb[(size_t)BB * CC * LL];        // 16.8 MB  x in bf16
__device__ bf16 g_wq[CQ * CC], g_wk[CQ * CC];      // 64 KB each
__device__ bf16 g_wv[(size_t)CC * CC];             // 512 KB
__device__ bf16 g_wo[(size_t)CC * CC];             // 512 KB
__device__ bf16 g_qb[(size_t)BB * CQ * LL];        // 2 MB   (pre-scaled by SCALE)
__device__ bf16 g_kb[(size_t)BB * CQ * LL];        // 2 MB
__device__ bf16 g_vb[(size_t)BB * CC * LL];        // 16.8 MB
__device__ bf16 g_av2[(size_t)BB * LL * CC];       // 16.8 MB  attention out, [b][l][c]

// ---------------------------------------------------------------------------
// Helpers
// ---------------------------------------------------------------------------
__device__ __forceinline__ void cp16(void* dst_smem, const void* src) {
    unsigned d = (unsigned)__cvta_generic_to_shared(dst_smem);
    asm volatile("cp.async.cg.shared.global [%0], [%1], 16;" :: "r"(d), "l"(src));
}
#define CP_COMMIT() asm volatile("cp.async.commit_group;")
#define CP_WAIT(N)  asm volatile("cp.async.wait_group " #N ";")

__device__ __forceinline__ void ldsm_x4(unsigned* r, unsigned s) {
    asm volatile("ldmatrix.sync.aligned.m8n8.x4.shared.b16 {%0,%1,%2,%3}, [%4];"
        : "=r"(r[0]), "=r"(r[1]), "=r"(r[2]), "=r"(r[3]) : "r"(s));
}
__device__ __forceinline__ void ldsm_x2(unsigned* r, unsigned s) {
    asm volatile("ldmatrix.sync.aligned.m8n8.x2.shared.b16 {%0,%1}, [%2];"
        : "=r"(r[0]), "=r"(r[1]) : "r"(s));
}
__device__ __forceinline__ void ldsm_x4t(unsigned* r, unsigned s) {
    asm volatile("ldmatrix.sync.aligned.m8n8.x4.trans.shared.b16 {%0,%1,%2,%3}, [%4];"
        : "=r"(r[0]), "=r"(r[1]), "=r"(r[2]), "=r"(r[3]) : "r"(s));
}
__device__ __forceinline__ void ldsm_x2t(unsigned* r, unsigned s) {
    asm volatile("ldmatrix.sync.aligned.m8n8.x2.trans.shared.b16 {%0,%1}, [%2];"
        : "=r"(r[0]), "=r"(r[1]) : "r"(s));
}

// D += A(16x16 row) * B(16x8 col), fp32 accum.
__device__ __forceinline__ void mma_bf16(float* c, const unsigned* a, const unsigned* b) {
    asm volatile(
        "mma.sync.aligned.m16n8k16.row.col.f32.bf16.bf16.f32 "
        "{%0,%1,%2,%3}, {%4,%5,%6,%7}, {%8,%9}, {%0,%1,%2,%3};"
        : "+f"(c[0]), "+f"(c[1]), "+f"(c[2]), "+f"(c[3])
        : "r"(a[0]), "r"(a[1]), "r"(a[2]), "r"(a[3]), "r"(b[0]), "r"(b[1]));
}

// pack two fp32 into one bf16x2 reg: low = lo, high = hi
__device__ __forceinline__ unsigned packbf(float lo, float hi) {
    unsigned d;
    asm("cvt.rn.bf16x2.f32 %0, %1, %2;" : "=r"(d) : "f"(hi), "f"(lo));
    return d;
}

// Frag maps (lane = 4g+t):
//  A: a0=A[g][2t,2t+1] a1=A[g+8][2t..] a2=A[g][8+2t..] a3=A[g+8][8+2t..]
//  B: b0=B[2t,2t+1][g] b1=B[8+2t..][g]   (B indexed [k][n])
//  C: c0=C[g][2t] c1=C[g][2t+1] c2=C[g+8][2t] c3=C[g+8][2t+1]
// C->A identity: two adjacent n8 C tiles == one k16 A frag (the FA2 trick).
// Smem strides 40/136 bf16 = 5/17 x16B units -> rows mod 8 distinct, LDSM-safe.

// ---------------------------------------------------------------------------
// Kernel 0: fp32 -> bf16 conversion of x and weights
// ---------------------------------------------------------------------------
#define NX  ((size_t)BB * CC * LL)
#define NWQ ((size_t)CQ * CC)
#define NWV ((size_t)CC * CC)
#define CVT_PAIRS ((NX + 2 * NWQ + 2 * NWV) / 2)
__global__ __launch_bounds__(256) void cvt_kernel(
    const float* __restrict__ x,  const float* __restrict__ Wq,
    const float* __restrict__ Wk, const float* __restrict__ Wv,
    const float* __restrict__ Wo)
{
    size_t i = ((size_t)blockIdx.x * 256 + threadIdx.x) * 2;
    if (i < NX) {
        *(bf162*)&g_xb[i] = __float22bfloat162_rn(*(const float2*)&x[i]); return;
    }
    i -= NX;
    if (i < NWQ) { *(bf162*)&g_wq[i] = __float22bfloat162_rn(*(const float2*)&Wq[i]); return; }
    i -= NWQ;
    if (i < NWQ) { *(bf162*)&g_wk[i] = __float22bfloat162_rn(*(const float2*)&Wk[i]); return; }
    i -= NWQ;
    if (i < NWV) { *(bf162*)&g_wv[i] = __float22bfloat162_rn(*(const float2*)&Wv[i]); return; }
    i -= NWV;
    if (i < NWV) { *(bf162*)&g_wo[i] = __float22bfloat162_rn(*(const float2*)&Wo[i]); }
}

// ---------------------------------------------------------------------------
// Kernel 1: fused QKV projection (unchanged from R11 except q pre-scaled).
// ---------------------------------------------------------------------------
#define QKV_A (64 * 40)
#define QKV_B (32 * 136)
#define QKV_STAGES 3
#define QKV_SMEM ((QKV_STAGES * (QKV_A + QKV_B)) * 2)
__global__ __launch_bounds__(256) void qkv_kernel(
    const float* __restrict__ bq, const float* __restrict__ bk,
    const float* __restrict__ bv)
{
    extern __shared__ bf16 sm[];
    bf16* As = sm;
    bf16* Bs = sm + QKV_STAGES * QKV_A;

    const int b  = blockIdx.z;
    const int rt = blockIdx.y;           // 0..9
    const int l0 = blockIdx.x * 128;

    const bf16* W; const float* bias; bf16* out; int row0; float osc;
    if (rt == 0)      { W = g_wq; bias = bq; out = g_qb + (size_t)b * CQ * LL; row0 = 0; osc = SCALE; }
    else if (rt == 1) { W = g_wk; bias = bk; out = g_kb + (size_t)b * CQ * LL; row0 = 0; osc = 1.f; }
    else              { W = g_wv; bias = bv; out = g_vb + (size_t)b * CC * LL; row0 = (rt - 2) * 64; osc = 1.f; }

    const int tid = threadIdx.x, w = tid >> 5, lane = tid & 31;
    const int g = lane >> 2, t = lane & 3;
    const int wm = (w >> 2) * 32, wn = (w & 3) * 32;
    const int l15 = lane & 15, hi = lane >> 4;
    const bf16* xb = g_xb + (size_t)b * CC * LL;
    const unsigned smA = (unsigned)__cvta_generic_to_shared(As);
    const unsigned smB = (unsigned)__cvta_generic_to_shared(Bs);

    float acc[2][4][4] = {};

    auto stage = [&](int buf, int k0) {
        bf16* Ab = As + buf * QKV_A;
        bf16* Bb = Bs + buf * QKV_B;
        {
            int m = tid >> 2, k8 = (tid & 3) * 8;
            cp16(Ab + m * 40 + k8, W + (size_t)(row0 + m) * CC + k0 + k8);
        }
        #pragma unroll
        for (int i = 0; i < 2; ++i) {
            int idx = tid + i * 256, k = idx >> 4, n8 = (idx & 15) * 8;
            cp16(Bb + k * 136 + n8, xb + (size_t)(k0 + k) * LL + l0 + n8);
        }
        CP_COMMIT();
    };

    const int NIT = CC / 32;
    stage(0, 0); stage(1, 32);
    int ld = 2, cb = 0;
    for (int it = 0; it < NIT; ++it) {
        if (it < NIT - 2) { CP_WAIT(1); } else { CP_WAIT(0); }
        __syncthreads();
        if (it + 2 < NIT) { stage(ld, (it + 2) * 32); ld = (ld == 2) ? 0 : ld + 1; }
        const unsigned a0 = smA + (unsigned)(cb * QKV_A) * 2;
        const unsigned b0a = smB + (unsigned)(cb * QKV_B) * 2;
        cb = (cb == 2) ? 0 : cb + 1;
        #pragma unroll
        for (int ks = 0; ks < 2; ++ks) {
            const int kk = ks * 16;
            unsigned af[2][4], bf[4][2];
            #pragma unroll
            for (int mi = 0; mi < 2; ++mi)
                ldsm_x4(af[mi], a0 + (unsigned)((wm + mi * 16 + l15) * 40 + kk) * 2 + hi * 16);
            #pragma unroll
            for (int ni = 0; ni < 4; ++ni)
                ldsm_x2t(bf[ni], b0a + (unsigned)((kk + l15) * 136 + wn + ni * 8) * 2);
            #pragma unroll
            for (int mi = 0; mi < 2; ++mi)
                #pragma unroll
                for (int ni = 0; ni < 4; ++ni)
                    mma_bf16(acc[mi][ni], af[mi], bf[ni]);
        }
    }

    #pragma unroll
    for (int mi = 0; mi < 2; ++mi) {
        int r0r = row0 + wm + mi * 16 + g;
        int r1r = r0r + 8;
        float b0v = bias[r0r], b1v = bias[r1r];
        #pragma unroll
        for (int ni = 0; ni < 4; ++ni) {
            int col = l0 + wn + ni * 8 + 2 * t;
            *(bf162*)&out[(size_t)r0r * LL + col] =
                __floats2bfloat162_rn((acc[mi][ni][0] + b0v) * osc, (acc[mi][ni][1] + b0v) * osc);
            *(bf162*)&out[(size_t)r1r * LL + col] =
                __floats2bfloat162_rn((acc[mi][ni][2] + b1v) * osc, (acc[mi][ni][3] + b1v) * osc);
        }
    }
}

// ---------------------------------------------------------------------------
// Kernel 2: FUSED flash attention: S=QtK -> online softmax -> acc += P*V.
// Block: 128 q x 128 c-chunk. 8 warps; warp = 16 q rows x full 128 k x 128 c.
// S C-frags repack in-register into P A-frags (C->A identity). No attn matrix
// in gmem. K/V tiles 3-stage cp.async; Q tile loaded once.
//   Qs[64][136]   [c][q]   A-frag via ldsm_x4t
//   Ks[s][64][136][c][k]   B-frag via ldsm_x4t (mats: c,c+8 x n,n+8)
//   Vs[s][128][136][c][k]  B-frag via ldsm_x4  (mats: n,n+8 x k,k+8)
// Writes av [b][l][c] bf16 (coalesced per q-row).
// ---------------------------------------------------------------------------
#define FA_QS (64 * 136)
#define FA_KS (64 * 136)
#define FA_VS (128 * 136)
#define FA_STAGES 3
#define FA_SMEM ((FA_QS + FA_STAGES * (FA_KS + FA_VS)) * 2)
__global__ __launch_bounds__(256, 1) void fa_kernel()
{
    extern __shared__ bf16 sm[];
    bf16* Qs = sm;
    bf16* Ks = sm + FA_QS;
    bf16* Vs = sm + FA_QS + FA_STAGES * FA_KS;

    const int b  = blockIdx.z;
    const int q0 = blockIdx.x * 128;
    const int c0 = blockIdx.y * 128;

    const int tid = threadIdx.x, w = tid >> 5, lane = tid & 31;
    const int g = lane >> 2, t = lane & 3;
    const int wq = w * 16;                       // warp's q-row base
    const bf16* qb = g_qb + (size_t)b * CQ * LL;
    const bf16* kb = g_kb + (size_t)b * CQ * LL;
    const bf16* vb = g_vb + (size_t)b * CC * LL + (size_t)c0 * LL;

    // ldsm per-lane address components
    const int aq_row = (lane >> 4) * 8 + (lane & 7);          // Q x4t: row(c)
    const int aq_col = wq + ((lane >> 3) & 1) * 8;            // Q x4t: col(q)
    const int bk_row = ((lane >> 3) & 1) * 8 + (lane & 7);    // K x4t: row(c)
    const int bk_csel = (lane >> 4) * 8;                      // K x4t: +col(k)
    const int v_row  = ((lane >> 4) & 1) * 8 + (lane & 7);    // V x4: row(c) in 16-grp
    const int v_csel = ((lane >> 3) & 1) * 8;                 // V x4: +col(k)

    const unsigned smQ = (unsigned)__cvta_generic_to_shared(Qs);
    const unsigned smK = (unsigned)__cvta_generic_to_shared(Ks);
    const unsigned smV = (unsigned)__cvta_generic_to_shared(Vs);

    // Load Q tile [c=64][q=128] once (group 0)
    #pragma unroll
    for (int i = 0; i < 4; ++i) {
        int idx = tid + i * 256, c = idx >> 4, n8 = (idx & 15) * 8;
        cp16(Qs + c * 136 + n8, qb + (size_t)c * LL + q0 + n8);
    }
    CP_COMMIT();

    auto stage = [&](int buf, int kt) {
        bf16* Kb = Ks + buf * FA_KS;
        bf16* Vb = Vs + buf * FA_VS;
        const int k0 = kt * 128;
        #pragma unroll
        for (int i = 0; i < 4; ++i) {
            int idx = tid + i * 256, c = idx >> 4, k8 = (idx & 15) * 8;
            cp16(Kb + c * 136 + k8, kb + (size_t)c * LL + k0 + k8);
        }
        #pragma unroll
        for (int i = 0; i < 8; ++i) {
            int idx = tid + i * 256, c = idx >> 4, k8 = (idx & 15) * 8;
            cp16(Vb + c * 136 + k8, vb + (size_t)c * LL + k0 + k8);
        }
        CP_COMMIT();
    };

    stage(0, 0); stage(1, 1);

    float acc[16][4] = {};
    float mx[2] = { -1e30f, -1e30f };
    float lsum[2] = { 0.f, 0.f };

    const int NIT = LL / 128;   // 16
    int ld = 2, cb = 0;
    for (int it = 0; it < NIT; ++it) {
        if (it < NIT - 2) { CP_WAIT(1); } else { CP_WAIT(0); }
        __syncthreads();
        if (it + 2 < NIT) { stage(ld, it + 2); ld = (ld == 2) ? 0 : ld + 1; }
        const unsigned k0s = smK + (unsigned)(cb * FA_KS) * 2;
        const unsigned v0s = smV + (unsigned)(cb * FA_VS) * 2;
        cb = (cb == 2) ? 0 : cb + 1;

        // ---- GEMM1: S[16q][128k] (q pre-scaled by SCALE) ----
        float sf[16][4];
        #pragma unroll
        for (int ni = 0; ni < 16; ++ni)
            #pragma unroll
            for (int j = 0; j < 4; ++j) sf[ni][j] = 0.f;

        #pragma unroll
        for (int cs = 0; cs < 4; ++cs) {
            const int kc = cs * 16;
            unsigned af[4];
            ldsm_x4t(af, smQ + (unsigned)((kc + aq_row) * 136 + aq_col) * 2);
            #pragma unroll
            for (int nj = 0; nj < 8; ++nj) {
                unsigned bq4[4];
                ldsm_x4t(bq4, k0s + (unsigned)((kc + bk_row) * 136 + nj * 16 + bk_csel) * 2);
                mma_bf16(sf[2 * nj],     af, bq4);
                mma_bf16(sf[2 * nj + 1], af, bq4 + 2);
            }
        }

        // ---- online softmax (rows g, g+8) ----
        float cm0 = -1e30f, cm1 = -1e30f;
        #pragma unroll
        for (int ni = 0; ni < 16; ++ni) {
            cm0 = fmaxf(cm0, fmaxf(sf[ni][0], sf[ni][1]));
            cm1 = fmaxf(cm1, fmaxf(sf[ni][2], sf[ni][3]));
        }
        cm0 = fmaxf(cm0, __shfl_xor_sync(0xffffffffu, cm0, 1));
        cm0 = fmaxf(cm0, __shfl_xor_sync(0xffffffffu, cm0, 2));
        cm1 = fmaxf(cm1, __shfl_xor_sync(0xffffffffu, cm1, 1));
        cm1 = fmaxf(cm1, __shfl_xor_sync(0xffffffffu, cm1, 2));
        const float mn0 = fmaxf(mx[0], cm0), mn1 = fmaxf(mx[1], cm1);
        const float f0 = __expf(mx[0] - mn0), f1 = __expf(mx[1] - mn1);
        mx[0] = mn0; mx[1] = mn1;

        float s0 = 0.f, s1 = 0.f;
        #pragma unroll
        for (int ni = 0; ni < 16; ++ni) {
            sf[ni][0] = __expf(sf[ni][0] - mn0);
            sf[ni][1] = __expf(sf[ni][1] - mn0);
            sf[ni][2] = __expf(sf[ni][2] - mn1);
            sf[ni][3] = __expf(sf[ni][3] - mn1);
            s0 += sf[ni][0] + sf[ni][1];
            s1 += sf[ni][2] + sf[ni][3];
        }
        s0 += __shfl_xor_sync(0xffffffffu, s0, 1);
        s0 += __shfl_xor_sync(0xffffffffu, s0, 2);
        s1 += __shfl_xor_sync(0xffffffffu, s1, 1);
        s1 += __shfl_xor_sync(0xffffffffu, s1, 2);
        lsum[0] = lsum[0] * f0 + s0;
        lsum[1] = lsum[1] * f1 + s1;

        #pragma unroll
        for (int ni = 0; ni < 16; ++ni) {
            acc[ni][0] *= f0; acc[ni][1] *= f0;
            acc[ni][2] *= f1; acc[ni][3] *= f1;
        }

        // ---- pack P: C-frags -> A-frags (in register) ----
        unsigned paf[8][4];
        #pragma unroll
        for (int ks = 0; ks < 8; ++ks) {
            paf[ks][0] = packbf(sf[2 * ks][0],     sf[2 * ks][1]);
            paf[ks][1] = packbf(sf[2 * ks][2],     sf[2 * ks][3]);
            paf[ks][2] = packbf(sf[2 * ks + 1][0], sf[2 * ks + 1][1]);
            paf[ks][3] = packbf(sf[2 * ks + 1][2], sf[2 * ks + 1][3]);
        }

        // ---- GEMM2: acc[16q][128c] += P[16q][128k] * V^T[128k][128c] ----
        #pragma unroll
        for (int ks = 0; ks < 8; ++ks) {
            const int kk = ks * 16;
            #pragma unroll
            for (int ci = 0; ci < 8; ++ci) {
                unsigned vf[4];
                ldsm_x4(vf, v0s + (unsigned)((ci * 16 + v_row) * 136 + kk + v_csel) * 2);
                mma_bf16(acc[2 * ci],     paf[ks], vf);
                mma_bf16(acc[2 * ci + 1], paf[ks], vf + 2);
            }
        }
    }

    // ---- epilogue: divide by l, write av [b][l][c] ----
    const float inv0 = 1.0f / lsum[0], inv1 = 1.0f / lsum[1];
    const int row0 = q0 + wq + g, row1 = row0 + 8;
    bf16* ob0 = g_av2 + ((size_t)b * LL + row0) * CC;
    bf16* ob1 = g_av2 + ((size_t)b * LL + row1) * CC;
    #pragma unroll
    for (int ni = 0; ni < 16; ++ni) {
        int col = c0 + ni * 8 + 2 * t;
        *(bf162*)&ob0[col] = __floats2bfloat162_rn(acc[ni][0] * inv0, acc[ni][1] * inv0);
        *(bf162*)&ob1[col] = __floats2bfloat162_rn(acc[ni][2] * inv1, acc[ni][3] * inv1);
    }
}

// ---------------------------------------------------------------------------
// Kernel 3: O projection + bias + residual (fp32 out). Block 128o x 128l.
// B now staged from av [l][c]: tile [l=128][c=32] stride 40, ldsm_x2 non-trans.
// ---------------------------------------------------------------------------
#define OP_A (128 * 40)
#define OP_B (128 * 40)
#define OP_STAGES 3
#define OP_SMEM ((OP_STAGES * (OP_A + OP_B)) * 2)
__global__ __launch_bounds__(256) void outproj_kernel(
    const float* __restrict__ x,
    const float* __restrict__ bo, float* __restrict__ out)
{
    extern __shared__ bf16 sm[];
    bf16* As = sm;                      // [3][128][40]  Wo tile [o][c]
    bf16* Bs = sm + OP_STAGES * OP_A;   // [3][128][40]  av tile [l][c]

    const int b  = blockIdx.z;
    const int r0 = blockIdx.y * 128;
    const int l0 = blockIdx.x * 128;

    const int tid = threadIdx.x, w = tid >> 5, lane = tid & 31;
    const int g = lane >> 2, t = lane & 3;
    const int wm = (w >> 2) * 64, wn = (w & 3) * 32;
    const int l15 = lane & 15, hi = lane >> 4;
    const int l7 = lane & 7, b8 = ((lane >> 3) & 1) * 8;
    const bf16* avb = g_av2 + (size_t)b * LL * CC;
    const unsigned smA = (unsigned)__cvta_generic_to_shared(As);
    const unsigned smB = (unsigned)__cvta_generic_to_shared(Bs);

    float acc[4][4][4] = {};

    auto stage = [&](int buf, int k0) {
        bf16* Ab = As + buf * OP_A;
        bf16* Bb = Bs + buf * OP_B;
        #pragma unroll
        for (int i = 0; i < 2; ++i) {   // 128x32 Wo tile
            int idx = tid + i * 256, m = idx >> 2, k8 = (idx & 3) * 8;
            cp16(Ab + m * 40 + k8, g_wo + (size_t)(r0 + m) * CC + k0 + k8);
        }
        #pragma unroll
        for (int i = 0; i < 2; ++i) {   // 128l x 32c av tile
            int idx = tid + i * 256, l = idx >> 2, c8 = (idx & 3) * 8;
            cp16(Bb + l * 40 + c8, avb + (size_t)(l0 + l) * CC + k0 + c8);
        }
        CP_COMMIT();
    };

    const int NIT = CC / 32;   // 16
    stage(0, 0); stage(1, 32);
    int ld = 2, cb = 0;
    for (int it = 0; it < NIT; ++it) {
        if (it < NIT - 2) { CP_WAIT(1); } else { CP_WAIT(0); }
        __syncthreads();
        if (it + 2 < NIT) { stage(ld, (it + 2) * 32); ld = (ld == 2) ? 0 : ld + 1; }
        const unsigned a0 = smA + (unsigned)(cb * OP_A) * 2;
        const unsigned b0a = smB + (unsigned)(cb * OP_B) * 2;
        cb = (cb == 2) ? 0 : cb + 1;
        #pragma unroll
        for (int ks = 0; ks < 2; ++ks) {
            const int kk = ks * 16;
            unsigned af[4][4], bf[4][2];
            #pragma unroll
            for (int mi = 0; mi < 4; ++mi)
                ldsm_x4(af[mi], a0 + (unsigned)((wm + mi * 16 + l15) * 40 + kk) * 2 + hi * 16);
            #pragma unroll
            for (int ni = 0; ni < 4; ++ni)
                ldsm_x2(bf[ni], b0a + (unsigned)((wn + ni * 8 + l7) * 40 + kk + b8) * 2);
            #pragma unroll
            for (int mi = 0; mi < 4; ++mi)
                #pragma unroll
                for (int ni = 0; ni < 4; ++ni)
                    mma_bf16(acc[mi][ni], af[mi], bf[ni]);
        }
    }

    #pragma unroll
    for (int mi = 0; mi < 4; ++mi) {
        int ch0 = r0 + wm + mi * 16 + g;
        int ch1 = ch0 + 8;
        float b0v = bo[ch0], b1v = bo[ch1];
        #pragma unroll
        for (int ni = 0; ni < 4; ++ni) {
            int col = l0 + wn + ni * 8 + 2 * t;
            size_t off0 = (size_t)b * CC * LL + (size_t)ch0 * LL + col;
            size_t off1 = (size_t)b * CC * LL + (size_t)ch1 * LL + col;
            float2 x0 = *(const float2*)&x[off0];
            float2 x1 = *(const float2*)&x[off1];
            *(float2*)&out[off0] = make_float2(acc[mi][ni][0] + b0v + x0.x,
                                               acc[mi][ni][1] + b0v + x0.y);
            *(float2*)&out[off1] = make_float2(acc[mi][ni][2] + b1v + x1.x,
                                               acc[mi][ni][3] + b1v + x1.y);
        }
    }
}

// ---------------------------------------------------------------------------
// Launch: 4 kernels on one stream, graph-capturable, no allocations.
// ---------------------------------------------------------------------------
extern "C" void kernel_launch(void* const* d_in, const int* in_sizes, int n_in,
                              void* d_out, int out_size)
{
    (void)in_sizes; (void)n_in; (void)out_size;
    const float* x  = (const float*)d_in[0];
    const float* Wq = (const float*)d_in[1];
    const float* bq = (const float*)d_in[2];
    const float* Wk = (const float*)d_in[3];
    const float* bk = (const float*)d_in[4];
    const float* Wv = (const float*)d_in[5];
    const float* bv = (const float*)d_in[6];
    const float* Wo = (const float*)d_in[7];
    const float* bo = (const float*)d_in[8];
    float* out = (float*)d_out;

    cudaFuncSetAttribute(qkv_kernel,     cudaFuncAttributeMaxDynamicSharedMemorySize, QKV_SMEM);
    cudaFuncSetAttribute(fa_kernel,      cudaFuncAttributeMaxDynamicSharedMemorySize, FA_SMEM);
    cudaFuncSetAttribute(outproj_kernel, cudaFuncAttributeMaxDynamicSharedMemorySize, OP_SMEM);

    dim3 blk(256);
    cvt_kernel    <<<(unsigned)((CVT_PAIRS + 255) / 256), blk>>>(x, Wq, Wk, Wv, Wo);
    qkv_kernel    <<<dim3(LL / 128, 10,       BB), blk, QKV_SMEM>>>(bq, bk, bv);
    fa_kernel     <<<dim3(LL / 128, CC / 128, BB), blk, FA_SMEM>>>();
    outproj_kernel<<<dim3(LL / 128, CC / 128, BB), blk, OP_SMEM>>>(x, bo, out);
}

// round 13
// speedup vs baseline: 7.0656x; 1.0155x over previous
#include <cuda_runtime.h>
#include <cuda_bf16.h>

// Shapes (fixed by the problem)
#define BB  8
#define CC  512
#define LL  2048
#define CQ  64
#define SCALE 0.125f   // CQK^-0.5 (exact power of 2; folded into q at qkv epilogue)

typedef __nv_bfloat16  bf16;
typedef __nv_bfloat162 bf162;

// ---------------------------------------------------------------------------
// Scratch (static __device__ arrays — no allocation anywhere)
// ---------------------------------------------------------------------------
__device__ bf16 g_xb[(size_t)BB * CC * LL];        // 16.8 MB  x in bf16
__device__ bf16 g_wq[CQ * CC], g_wk[CQ * CC];      // 64 KB each
__device__ bf16 g_wv[(size_t)CC * CC];             // 512 KB
__device__ bf16 g_wo[(size_t)CC * CC];             // 512 KB
__device__ bf16 g_qb[(size_t)BB * CQ * LL];        // 2 MB   (pre-scaled by SCALE)
__device__ bf16 g_kb[(size_t)BB * CQ * LL];        // 2 MB
__device__ bf16 g_vb[(size_t)BB * CC * LL];        // 16.8 MB
__device__ bf16 g_av2[(size_t)BB * LL * CC];       // 16.8 MB  attention out, [b][l][c]

// ---------------------------------------------------------------------------
// Helpers
// ---------------------------------------------------------------------------
__device__ __forceinline__ void cp16(void* dst_smem, const void* src) {
    unsigned d = (unsigned)__cvta_generic_to_shared(dst_smem);
    asm volatile("cp.async.cg.shared.global [%0], [%1], 16;" :: "r"(d), "l"(src));
}
#define CP_COMMIT() asm volatile("cp.async.commit_group;")
#define CP_WAIT(N)  asm volatile("cp.async.wait_group " #N ";")

__device__ __forceinline__ void ldsm_x4(unsigned* r, unsigned s) {
    asm volatile("ldmatrix.sync.aligned.m8n8.x4.shared.b16 {%0,%1,%2,%3}, [%4];"
        : "=r"(r[0]), "=r"(r[1]), "=r"(r[2]), "=r"(r[3]) : "r"(s));
}
__device__ __forceinline__ void ldsm_x2(unsigned* r, unsigned s) {
    asm volatile("ldmatrix.sync.aligned.m8n8.x2.shared.b16 {%0,%1}, [%2];"
        : "=r"(r[0]), "=r"(r[1]) : "r"(s));
}
__device__ __forceinline__ void ldsm_x4t(unsigned* r, unsigned s) {
    asm volatile("ldmatrix.sync.aligned.m8n8.x4.trans.shared.b16 {%0,%1,%2,%3}, [%4];"
        : "=r"(r[0]), "=r"(r[1]), "=r"(r[2]), "=r"(r[3]) : "r"(s));
}
__device__ __forceinline__ void ldsm_x2t(unsigned* r, unsigned s) {
    asm volatile("ldmatrix.sync.aligned.m8n8.x2.trans.shared.b16 {%0,%1}, [%2];"
        : "=r"(r[0]), "=r"(r[1]) : "r"(s));
}

// D += A(16x16 row) * B(16x8 col), fp32 accum.
__device__ __forceinline__ void mma_bf16(float* c, const unsigned* a, const unsigned* b) {
    asm volatile(
        "mma.sync.aligned.m16n8k16.row.col.f32.bf16.bf16.f32 "
        "{%0,%1,%2,%3}, {%4,%5,%6,%7}, {%8,%9}, {%0,%1,%2,%3};"
        : "+f"(c[0]), "+f"(c[1]), "+f"(c[2]), "+f"(c[3])
        : "r"(a[0]), "r"(a[1]), "r"(a[2]), "r"(a[3]), "r"(b[0]), "r"(b[1]));
}

// pack two fp32 into one bf16x2 reg: low = lo, high = hi
__device__ __forceinline__ unsigned packbf(float lo, float hi) {
    unsigned d;
    asm("cvt.rn.bf16x2.f32 %0, %1, %2;" : "=r"(d) : "f"(hi), "f"(lo));
    return d;
}

// Frag maps (lane = 4g+t):
//  A: a0=A[g][2t,2t+1] a1=A[g+8][2t..] a2=A[g][8+2t..] a3=A[g+8][8+2t..]
//  B: b0=B[2t,2t+1][g] b1=B[8+2t..][g]   (B indexed [k][n])
//  C: c0=C[g][2t] c1=C[g][2t+1] c2=C[g+8][2t] c3=C[g+8][2t+1]
// C->A identity: two adjacent n8 C tiles == one k16 A frag (the FA2 trick).
// Smem strides 40/72/136 bf16 = 5/9/17 x16B units -> rows mod 8 distinct, LDSM-safe.

// ---------------------------------------------------------------------------
// Kernel 0: fp32 -> bf16 conversion of x and weights
// ---------------------------------------------------------------------------
#define NX  ((size_t)BB * CC * LL)
#define NWQ ((size_t)CQ * CC)
#define NWV ((size_t)CC * CC)
#define CVT_PAIRS ((NX + 2 * NWQ + 2 * NWV) / 2)
__global__ __launch_bounds__(256) void cvt_kernel(
    const float* __restrict__ x,  const float* __restrict__ Wq,
    const float* __restrict__ Wk, const float* __restrict__ Wv,
    const float* __restrict__ Wo)
{
    size_t i = ((size_t)blockIdx.x * 256 + threadIdx.x) * 2;
    if (i < NX) {
        *(bf162*)&g_xb[i] = __float22bfloat162_rn(*(const float2*)&x[i]); return;
    }
    i -= NX;
    if (i < NWQ) { *(bf162*)&g_wq[i] = __float22bfloat162_rn(*(const float2*)&Wq[i]); return; }
    i -= NWQ;
    if (i < NWQ) { *(bf162*)&g_wk[i] = __float22bfloat162_rn(*(const float2*)&Wk[i]); return; }
    i -= NWQ;
    if (i < NWV) { *(bf162*)&g_wv[i] = __float22bfloat162_rn(*(const float2*)&Wv[i]); return; }
    i -= NWV;
    if (i < NWV) { *(bf162*)&g_wo[i] = __float22bfloat162_rn(*(const float2*)&Wo[i]); }
}

// ---------------------------------------------------------------------------
// Kernel 1: fused QKV projection (unchanged, trusted-passing; q pre-scaled).
// ---------------------------------------------------------------------------
#define QKV_A (64 * 40)
#define QKV_B (32 * 136)
#define QKV_STAGES 3
#define QKV_SMEM ((QKV_STAGES * (QKV_A + QKV_B)) * 2)
__global__ __launch_bounds__(256) void qkv_kernel(
    const float* __restrict__ bq, const float* __restrict__ bk,
    const float* __restrict__ bv)
{
    extern __shared__ bf16 sm[];
    bf16* As = sm;
    bf16* Bs = sm + QKV_STAGES * QKV_A;

    const int b  = blockIdx.z;
    const int rt = blockIdx.y;           // 0..9
    const int l0 = blockIdx.x * 128;

    const bf16* W; const float* bias; bf16* out; int row0; float osc;
    if (rt == 0)      { W = g_wq; bias = bq; out = g_qb + (size_t)b * CQ * LL; row0 = 0; osc = SCALE; }
    else if (rt == 1) { W = g_wk; bias = bk; out = g_kb + (size_t)b * CQ * LL; row0 = 0; osc = 1.f; }
    else              { W = g_wv; bias = bv; out = g_vb + (size_t)b * CC * LL; row0 = (rt - 2) * 64; osc = 1.f; }

    const int tid = threadIdx.x, w = tid >> 5, lane = tid & 31;
    const int g = lane >> 2, t = lane & 3;
    const int wm = (w >> 2) * 32, wn = (w & 3) * 32;
    const int l15 = lane & 15, hi = lane >> 4;
    const bf16* xb = g_xb + (size_t)b * CC * LL;
    const unsigned smA = (unsigned)__cvta_generic_to_shared(As);
    const unsigned smB = (unsigned)__cvta_generic_to_shared(Bs);

    float acc[2][4][4] = {};

    auto stage = [&](int buf, int k0) {
        bf16* Ab = As + buf * QKV_A;
        bf16* Bb = Bs + buf * QKV_B;
        {
            int m = tid >> 2, k8 = (tid & 3) * 8;
            cp16(Ab + m * 40 + k8, W + (size_t)(row0 + m) * CC + k0 + k8);
        }
        #pragma unroll
        for (int i = 0; i < 2; ++i) {
            int idx = tid + i * 256, k = idx >> 4, n8 = (idx & 15) * 8;
            cp16(Bb + k * 136 + n8, xb + (size_t)(k0 + k) * LL + l0 + n8);
        }
        CP_COMMIT();
    };

    const int NIT = CC / 32;
    stage(0, 0); stage(1, 32);
    int ld = 2, cb = 0;
    for (int it = 0; it < NIT; ++it) {
        if (it < NIT - 2) { CP_WAIT(1); } else { CP_WAIT(0); }
        __syncthreads();
        if (it + 2 < NIT) { stage(ld, (it + 2) * 32); ld = (ld == 2) ? 0 : ld + 1; }
        const unsigned a0 = smA + (unsigned)(cb * QKV_A) * 2;
        const unsigned b0a = smB + (unsigned)(cb * QKV_B) * 2;
        cb = (cb == 2) ? 0 : cb + 1;
        #pragma unroll
        for (int ks = 0; ks < 2; ++ks) {
            const int kk = ks * 16;
            unsigned af[2][4], bf[4][2];
            #pragma unroll
            for (int mi = 0; mi < 2; ++mi)
                ldsm_x4(af[mi], a0 + (unsigned)((wm + mi * 16 + l15) * 40 + kk) * 2 + hi * 16);
            #pragma unroll
            for (int ni = 0; ni < 4; ++ni)
                ldsm_x2t(bf[ni], b0a + (unsigned)((kk + l15) * 136 + wn + ni * 8) * 2);
            #pragma unroll
            for (int mi = 0; mi < 2; ++mi)
                #pragma unroll
                for (int ni = 0; ni < 4; ++ni)
                    mma_bf16(acc[mi][ni], af[mi], bf[ni]);
        }
    }

    #pragma unroll
    for (int mi = 0; mi < 2; ++mi) {
        int r0r = row0 + wm + mi * 16 + g;
        int r1r = r0r + 8;
        float b0v = bias[r0r], b1v = bias[r1r];
        #pragma unroll
        for (int ni = 0; ni < 4; ++ni) {
            int col = l0 + wn + ni * 8 + 2 * t;
            *(bf162*)&out[(size_t)r0r * LL + col] =
                __floats2bfloat162_rn((acc[mi][ni][0] + b0v) * osc, (acc[mi][ni][1] + b0v) * osc);
            *(bf162*)&out[(size_t)r1r * LL + col] =
                __floats2bfloat162_rn((acc[mi][ni][2] + b1v) * osc, (acc[mi][ni][3] + b1v) * osc);
        }
    }
}

// ---------------------------------------------------------------------------
// Kernel 2: FUSED flash attention, v2 — softmax computed ONCE per q-row.
// Block: 64 q-rows x full C=512, 256 threads (8 warps). Grid (32 q-tiles, 8 b).
// Per 64-k tile:
//   warps 0-3 (one per 16-q group): GEMM1 S=QtK (16q x 64k), online softmax,
//     rescale own acc, pack P C-frags -> A-frags (in reg), store packed P to
//     smem + row rescale factors f[].
//   barrier; warps 4-7: read f, rescale acc, ldsm P frags from smem.
//   all 8 warps: GEMM2 acc(16q x 256c) += P(16q x 64k) * V^T.
// Smem (bf16 elems): Qs[64][72] @0 | Ks[2][64][72] @4608 | Vs[2][512][72]
//   @13824 | Ps[64][72] @87552 | f[64],linv[64] fp32 @ byte 184320.
// All strides 72 bf16 = 9 x16B units -> rows mod 8 distinct (LDSM/STS safe).
// ---------------------------------------------------------------------------
#define FA_SMEM (92160 * 2 + 512)
__global__ __launch_bounds__(256, 1) void fa_kernel()
{
    extern __shared__ bf16 sm[];
    bf16* Qs = sm;
    bf16* Ks = sm + 4608;
    bf16* Vs = sm + 13824;
    bf16* Ps = sm + 87552;
    float* fS   = (float*)(sm + 92160);
    float* linv = fS + 64;

    const int b  = blockIdx.y;
    const int q0 = blockIdx.x * 64;

    const int tid = threadIdx.x, w = tid >> 5, lane = tid & 31;
    const int g = lane >> 2, t = lane & 3;
    const int qg = (w & 3) * 16;      // this warp's q-group rows (phase1 + output)
    const int ch = (w >> 2) * 256;    // this warp's c-half (GEMM2 + output)
    const bf16* qb = g_qb + (size_t)b * CQ * LL;
    const bf16* kb = g_kb + (size_t)b * CQ * LL;
    const bf16* vb = g_vb + (size_t)b * CC * LL;

    const unsigned smQ = (unsigned)__cvta_generic_to_shared(Qs);
    const unsigned smK = (unsigned)__cvta_generic_to_shared(Ks);
    const unsigned smV = (unsigned)__cvta_generic_to_shared(Vs);
    const unsigned smP = (unsigned)__cvta_generic_to_shared(Ps);
    unsigned* Ps32 = (unsigned*)Ps;

    // per-lane ldsm address components (patterns validated in prior rounds)
    const int aq_row = (lane >> 4) * 8 + (lane & 7);        // Q x4t row(c)
    const int aq_col = qg + ((lane >> 3) & 1) * 8;          // Q x4t col(q)
    const int bk_row = ((lane >> 3) & 1) * 8 + (lane & 7);  // K x4t row(c)
    const int bk_csel = (lane >> 4) * 8;                    // K x4t +col(k)
    const int v_row  = ((lane >> 4) & 1) * 8 + (lane & 7);  // V x4 row(c) in 16-grp
    const int v_csel = ((lane >> 3) & 1) * 8;               // V x4 +col(k)
    const int p_row  = lane & 15, p_hi = (lane >> 4) * 8;   // P x4 (non-trans)

    // load Q tile [c=64][q=64] once
    #pragma unroll
    for (int i = 0; i < 2; ++i) {
        int idx = tid + i * 256, c = idx >> 3, q8 = (idx & 7) * 8;
        cp16(Qs + c * 72 + q8, qb + (size_t)c * LL + q0 + q8);
    }
    CP_COMMIT();

    auto stage = [&](int buf, int kt) {
        bf16* Kb = Ks + buf * 4608;
        bf16* Vb = Vs + buf * 36864;
        const int k0 = kt * 64;
        #pragma unroll
        for (int i = 0; i < 2; ++i) {         // K: 64c x 64k
            int idx = tid + i * 256, c = idx >> 3, k8 = (idx & 7) * 8;
            cp16(Kb + c * 72 + k8, kb + (size_t)c * LL + k0 + k8);
        }
        #pragma unroll
        for (int i = 0; i < 16; ++i) {        // V: 512c x 64k
            int idx = tid + i * 256, c = idx >> 3, k8 = (idx & 7) * 8;
            cp16(Vb + c * 72 + k8, vb + (size_t)c * LL + k0 + k8);
        }
        CP_COMMIT();
    };
    stage(0, 0); stage(1, 1);

    float acc[32][4] = {};
    float mx0 = -1e30f, mx1 = -1e30f, ls0 = 0.f, ls1 = 0.f;

    const int NIT = LL / 64;   // 32
    for (int it = 0; it < NIT; ++it) {
        if (it < NIT - 1) { CP_WAIT(1); } else { CP_WAIT(0); }
        __syncthreads();
        const int cb = it & 1;
        const unsigned k0s = smK + (unsigned)(cb * 4608) * 2;
        const unsigned v0s = smV + (unsigned)(cb * 36864) * 2;

        unsigned paf[4][4];

        if (w < 4) {
            // ---- GEMM1: S[16q][64k] ----
            float sf[8][4];
            #pragma unroll
            for (int ni = 0; ni < 8; ++ni)
                #pragma unroll
                for (int j = 0; j < 4; ++j) sf[ni][j] = 0.f;
            #pragma unroll
            for (int cs = 0; cs < 4; ++cs) {
                unsigned af[4];
                ldsm_x4t(af, smQ + (unsigned)((cs * 16 + aq_row) * 72 + aq_col) * 2);
                #pragma unroll
                for (int nj = 0; nj < 4; ++nj) {
                    unsigned bq4[4];
                    ldsm_x4t(bq4, k0s + (unsigned)((cs * 16 + bk_row) * 72 + nj * 16 + bk_csel) * 2);
                    mma_bf16(sf[2 * nj],     af, bq4);
                    mma_bf16(sf[2 * nj + 1], af, bq4 + 2);
                }
            }

            // ---- online softmax (rows qg+g, qg+g+8) ----
            float cm0 = -1e30f, cm1 = -1e30f;
            #pragma unroll
            for (int ni = 0; ni < 8; ++ni) {
                cm0 = fmaxf(cm0, fmaxf(sf[ni][0], sf[ni][1]));
                cm1 = fmaxf(cm1, fmaxf(sf[ni][2], sf[ni][3]));
            }
            cm0 = fmaxf(cm0, __shfl_xor_sync(0xffffffffu, cm0, 1));
            cm0 = fmaxf(cm0, __shfl_xor_sync(0xffffffffu, cm0, 2));
            cm1 = fmaxf(cm1, __shfl_xor_sync(0xffffffffu, cm1, 1));
            cm1 = fmaxf(cm1, __shfl_xor_sync(0xffffffffu, cm1, 2));
            const float mn0 = fmaxf(mx0, cm0), mn1 = fmaxf(mx1, cm1);
            const float f0 = __expf(mx0 - mn0), f1 = __expf(mx1 - mn1);
            mx0 = mn0; mx1 = mn1;

            float s0 = 0.f, s1 = 0.f;
            #pragma unroll
            for (int ni = 0; ni < 8; ++ni) {
                sf[ni][0] = __expf(sf[ni][0] - mn0);
                sf[ni][1] = __expf(sf[ni][1] - mn0);
                sf[ni][2] = __expf(sf[ni][2] - mn1);
                sf[ni][3] = __expf(sf[ni][3] - mn1);
                s0 += sf[ni][0] + sf[ni][1];
                s1 += sf[ni][2] + sf[ni][3];
            }
            s0 += __shfl_xor_sync(0xffffffffu, s0, 1);
            s0 += __shfl_xor_sync(0xffffffffu, s0, 2);
            s1 += __shfl_xor_sync(0xffffffffu, s1, 1);
            s1 += __shfl_xor_sync(0xffffffffu, s1, 2);
            ls0 = ls0 * f0 + s0;
            ls1 = ls1 * f1 + s1;

            // rescale own acc
            #pragma unroll
            for (int ni = 0; ni < 32; ++ni) {
                acc[ni][0] *= f0; acc[ni][1] *= f0;
                acc[ni][2] *= f1; acc[ni][3] *= f1;
            }

            // pack C->A and store packed P to smem (word stride 36; banks 4g+t)
            #pragma unroll
            for (int ks = 0; ks < 4; ++ks) {
                paf[ks][0] = packbf(sf[2 * ks][0],     sf[2 * ks][1]);
                paf[ks][1] = packbf(sf[2 * ks][2],     sf[2 * ks][3]);
                paf[ks][2] = packbf(sf[2 * ks + 1][0], sf[2 * ks + 1][1]);
                paf[ks][3] = packbf(sf[2 * ks + 1][2], sf[2 * ks + 1][3]);
                Ps32[(qg + g    ) * 36 + ks * 8 +     t] = paf[ks][0];
                Ps32[(qg + g + 8) * 36 + ks * 8 +     t] = paf[ks][1];
                Ps32[(qg + g    ) * 36 + ks * 8 + 4 + t] = paf[ks][2];
                Ps32[(qg + g + 8) * 36 + ks * 8 + 4 + t] = paf[ks][3];
            }
            if (t == 0) { fS[qg + g] = f0; fS[qg + g + 8] = f1; }
        }
        __syncthreads();

        if (w >= 4) {
            const float f0 = fS[qg + g], f1 = fS[qg + g + 8];
            #pragma unroll
            for (int ni = 0; ni < 32; ++ni) {
                acc[ni][0] *= f0; acc[ni][1] *= f0;
                acc[ni][2] *= f1; acc[ni][3] *= f1;
            }
            #pragma unroll
            for (int ks = 0; ks < 4; ++ks)
                ldsm_x4(paf[ks], smP + (unsigned)((qg + p_row) * 72 + ks * 16 + p_hi) * 2);
        }

        // ---- GEMM2: acc[16q][256c] += P[16q][64k] * V^T ----
        #pragma unroll
        for (int ks = 0; ks < 4; ++ks) {
            const int kk = ks * 16;
            #pragma unroll
            for (int ci = 0; ci < 16; ++ci) {
                unsigned vf[4];
                ldsm_x4(vf, v0s + (unsigned)((ch + ci * 16 + v_row) * 72 + kk + v_csel) * 2);
                mma_bf16(acc[2 * ci],     paf[ks], vf);
                mma_bf16(acc[2 * ci + 1], paf[ks], vf + 2);
            }
        }
        __syncthreads();
        if (it + 2 < NIT) stage(cb, it + 2);
    }

    // ---- epilogue ----
    if (w < 4 && t == 0) { linv[qg + g] = 1.f / ls0; linv[qg + g + 8] = 1.f / ls1; }
    __syncthreads();
    const float i0 = linv[qg + g], i1 = linv[qg + g + 8];
    const int row0 = q0 + qg + g, row1 = row0 + 8;
    bf16* ob0 = g_av2 + ((size_t)b * LL + row0) * CC;
    bf16* ob1 = g_av2 + ((size_t)b * LL + row1) * CC;
    #pragma unroll
    for (int ni = 0; ni < 32; ++ni) {
        int col = ch + ni * 8 + 2 * t;
        *(bf162*)&ob0[col] = __floats2bfloat162_rn(acc[ni][0] * i0, acc[ni][1] * i0);
        *(bf162*)&ob1[col] = __floats2bfloat162_rn(acc[ni][2] * i1, acc[ni][3] * i1);
    }
}

// ---------------------------------------------------------------------------
// Kernel 3: O projection + bias + residual (unchanged, trusted-passing).
// ---------------------------------------------------------------------------
#define OP_A (128 * 40)
#define OP_B (128 * 40)
#define OP_STAGES 3
#define OP_SMEM ((OP_STAGES * (OP_A + OP_B)) * 2)
__global__ __launch_bounds__(256) void outproj_kernel(
    const float* __restrict__ x,
    const float* __restrict__ bo, float* __restrict__ out)
{
    extern __shared__ bf16 sm[];
    bf16* As = sm;                      // [3][128][40]  Wo tile [o][c]
    bf16* Bs = sm + OP_STAGES * OP_A;   // [3][128][40]  av tile [l][c]

    const int b  = blockIdx.z;
    const int r0 = blockIdx.y * 128;
    const int l0 = blockIdx.x * 128;

    const int tid = threadIdx.x, w = tid >> 5, lane = tid & 31;
    const int g = lane >> 2, t = lane & 3;
    const int wm = (w >> 2) * 64, wn = (w & 3) * 32;
    const int l15 = lane & 15, hi = lane >> 4;
    const int l7 = lane & 7, b8 = ((lane >> 3) & 1) * 8;
    const bf16* avb = g_av2 + (size_t)b * LL * CC;
    const unsigned smA = (unsigned)__cvta_generic_to_shared(As);
    const unsigned smB = (unsigned)__cvta_generic_to_shared(Bs);

    float acc[4][4][4] = {};

    auto stage = [&](int buf, int k0) {
        bf16* Ab = As + buf * OP_A;
        bf16* Bb = Bs + buf * OP_B;
        #pragma unroll
        for (int i = 0; i < 2; ++i) {
            int idx = tid + i * 256, m = idx >> 2, k8 = (idx & 3) * 8;
            cp16(Ab + m * 40 + k8, g_wo + (size_t)(r0 + m) * CC + k0 + k8);
        }
        #pragma unroll
        for (int i = 0; i < 2; ++i) {
            int idx = tid + i * 256, l = idx >> 2, c8 = (idx & 3) * 8;
            cp16(Bb + l * 40 + c8, avb + (size_t)(l0 + l) * CC + k0 + c8);
        }
        CP_COMMIT();
    };

    const int NIT = CC / 32;   // 16
    stage(0, 0); stage(1, 32);
    int ld = 2, cb = 0;
    for (int it = 0; it < NIT; ++it) {
        if (it < NIT - 2) { CP_WAIT(1); } else { CP_WAIT(0); }
        __syncthreads();
        if (it + 2 < NIT) { stage(ld, (it + 2) * 32); ld = (ld == 2) ? 0 : ld + 1; }
        const unsigned a0 = smA + (unsigned)(cb * OP_A) * 2;
        const unsigned b0a = smB + (unsigned)(cb * OP_B) * 2;
        cb = (cb == 2) ? 0 : cb + 1;
        #pragma unroll
        for (int ks = 0; ks < 2; ++ks) {
            const int kk = ks * 16;
            unsigned af[4][4], bf[4][2];
            #pragma unroll
            for (int mi = 0; mi < 4; ++mi)
                ldsm_x4(af[mi], a0 + (unsigned)((wm + mi * 16 + l15) * 40 + kk) * 2 + hi * 16);
            #pragma unroll
            for (int ni = 0; ni < 4; ++ni)
                ldsm_x2(bf[ni], b0a + (unsigned)((wn + ni * 8 + l7) * 40 + kk + b8) * 2);
            #pragma unroll
            for (int mi = 0; mi < 4; ++mi)
                #pragma unroll
                for (int ni = 0; ni < 4; ++ni)
                    mma_bf16(acc[mi][ni], af[mi], bf[ni]);
        }
    }

    #pragma unroll
    for (int mi = 0; mi < 4; ++mi) {
        int ch0 = r0 + wm + mi * 16 + g;
        int ch1 = ch0 + 8;
        float b0v = bo[ch0], b1v = bo[ch1];
        #pragma unroll
        for (int ni = 0; ni < 4; ++ni) {
            int col = l0 + wn + ni * 8 + 2 * t;
            size_t off0 = (size_t)b * CC * LL + (size_t)ch0 * LL + col;
            size_t off1 = (size_t)b * CC * LL + (size_t)ch1 * LL + col;
            float2 x0 = *(const float2*)&x[off0];
            float2 x1 = *(const float2*)&x[off1];
            *(float2*)&out[off0] = make_float2(acc[mi][ni][0] + b0v + x0.x,
                                               acc[mi][ni][1] + b0v + x0.y);
            *(float2*)&out[off1] = make_float2(acc[mi][ni][2] + b1v + x1.x,
                                               acc[mi][ni][3] + b1v + x1.y);
        }
    }
}

// ---------------------------------------------------------------------------
// Launch: 4 kernels on one stream, graph-capturable, no allocations.
// ---------------------------------------------------------------------------
extern "C" void kernel_launch(void* const* d_in, const int* in_sizes, int n_in,
                              void* d_out, int out_size)
{
    (void)in_sizes; (void)n_in; (void)out_size;
    const float* x  = (const float*)d_in[0];
    const float* Wq = (const float*)d_in[1];
    const float* bq = (const float*)d_in[2];
    const float* Wk = (const float*)d_in[3];
    const float* bk = (const float*)d_in[4];
    const float* Wv = (const float*)d_in[5];
    const float* bv = (const float*)d_in[6];
    const float* Wo = (const float*)d_in[7];
    const float* bo = (const float*)d_in[8];
    float* out = (float*)d_out;

    cudaFuncSetAttribute(qkv_kernel,     cudaFuncAttributeMaxDynamicSharedMemorySize, QKV_SMEM);
    cudaFuncSetAttribute(fa_kernel,      cudaFuncAttributeMaxDynamicSharedMemorySize, FA_SMEM);
    cudaFuncSetAttribute(outproj_kernel, cudaFuncAttributeMaxDynamicSharedMemorySize, OP_SMEM);

    dim3 blk(256);
    cvt_kernel    <<<(unsigned)((CVT_PAIRS + 255) / 256), blk>>>(x, Wq, Wk, Wv, Wo);
    qkv_kernel    <<<dim3(LL / 128, 10,       BB), blk, QKV_SMEM>>>(bq, bk, bv);
    fa_kernel     <<<dim3(LL / 64,  BB          ), blk, FA_SMEM>>>();
    outproj_kernel<<<dim3(LL / 128, CC / 128, BB), blk, OP_SMEM>>>(x, bo, out);
}